// round 7
// baseline (speedup 1.0000x reference)
#include <cuda_runtime.h>
#include <math.h>

constexpr int SEQ  = 2048;
constexpr int CH   = 1024;
constexpr int NB   = 16;
constexpr int DH   = 64;
constexpr int CROP = 2048;

// ---------------- scratch ----------------
__device__ float g_xq[SEQ * CH];
__device__ float g_xk[SEQ * CH];
__device__ float g_xv[SEQ * CH];
__device__ float g_q [SEQ * CH];
__device__ float g_k [SEQ * CH];
__device__ float g_v [SEQ * CH];
__device__ float g_o [SEQ * CH];
__device__ float g_qk[(size_t)NB * SEQ * SEQ];   // fallback if out buffer too small

// ---------------- tf32 helpers ----------------
__device__ __forceinline__ unsigned f2t(float f) {
    unsigned u; asm("cvt.rna.tf32.f32 %0, %1;" : "=r"(u) : "f"(f)); return u;
}
__device__ __forceinline__ void mma8(float c[4], const unsigned a[4], const unsigned b[2]) {
    asm volatile(
        "mma.sync.aligned.m16n8k8.row.col.f32.tf32.tf32.f32 "
        "{%0,%1,%2,%3},{%4,%5,%6,%7},{%8,%9},{%0,%1,%2,%3};"
        : "+f"(c[0]), "+f"(c[1]), "+f"(c[2]), "+f"(c[3])
        : "r"(a[0]), "r"(a[1]), "r"(a[2]), "r"(a[3]), "r"(b[0]), "r"(b[1]));
}

// =================================================================================
// Batched TF32 GEMM: C[z] = A @ B[z], A:[2048x1024], B:[1024x1024] row-major.
// =================================================================================
__global__ __launch_bounds__(256) void gemm_xw(
    const float* __restrict__ A,
    const float* __restrict__ B0, const float* __restrict__ B1, const float* __restrict__ B2,
    float* __restrict__ C0, float* __restrict__ C1, float* __restrict__ C2) {
    __shared__ unsigned sA[128][36];
    __shared__ unsigned sB[32][136];

    const float* B = blockIdx.z == 0 ? B0 : (blockIdx.z == 1 ? B1 : B2);
    float*       C = blockIdx.z == 0 ? C0 : (blockIdx.z == 1 ? C1 : C2);

    const int tid = threadIdx.x, lane = tid & 31, wid = tid >> 5;
    const int i0 = blockIdx.y * 128, j0 = blockIdx.x * 128;
    const int wm0 = (wid >> 2) * 64, wn0 = (wid & 3) * 32;
    const int g = lane >> 2, l = lane & 3;

    float4 pa[4], pb[4];

    auto loadT = [&](int k0) {
        #pragma unroll
        for (int n = 0; n < 4; n++) {
            int f = tid + n * 256, r = f >> 3, c = (f & 7) * 4;
            pa[n] = *(const float4*)(A + (size_t)(i0 + r) * CH + k0 + c);
        }
        #pragma unroll
        for (int n = 0; n < 4; n++) {
            int f = tid + n * 256, r = f >> 5, c = (f & 31) * 4;
            pb[n] = *(const float4*)(B + (size_t)(k0 + r) * CH + j0 + c);
        }
    };
    auto storeT = [&]() {
        #pragma unroll
        for (int n = 0; n < 4; n++) {
            int f = tid + n * 256, r = f >> 3, c = (f & 7) * 4;
            sA[r][c] = f2t(pa[n].x); sA[r][c + 1] = f2t(pa[n].y);
            sA[r][c + 2] = f2t(pa[n].z); sA[r][c + 3] = f2t(pa[n].w);
        }
        #pragma unroll
        for (int n = 0; n < 4; n++) {
            int f = tid + n * 256, r = f >> 5, c = (f & 31) * 4;
            sB[r][c] = f2t(pb[n].x); sB[r][c + 1] = f2t(pb[n].y);
            sB[r][c + 2] = f2t(pb[n].z); sB[r][c + 3] = f2t(pb[n].w);
        }
    };

    float acc[4][4][4] = {};
    loadT(0); storeT(); __syncthreads();

    for (int k0 = 0; k0 < CH; k0 += 32) {
        bool nx = (k0 + 32) < CH;
        if (nx) loadT(k0 + 32);
        #pragma unroll
        for (int ks = 0; ks < 4; ks++) {
            int kk = ks * 8;
            unsigned af[4][4], bf[4][2];
            #pragma unroll
            for (int mt = 0; mt < 4; mt++) {
                int m = wm0 + mt * 16 + g;
                af[mt][0] = sA[m][kk + l];       af[mt][1] = sA[m + 8][kk + l];
                af[mt][2] = sA[m][kk + 4 + l];   af[mt][3] = sA[m + 8][kk + 4 + l];
            }
            #pragma unroll
            for (int nt = 0; nt < 4; nt++) {
                int n = wn0 + nt * 8 + g;
                bf[nt][0] = sB[kk + l][n];       bf[nt][1] = sB[kk + 4 + l][n];
            }
            #pragma unroll
            for (int mt = 0; mt < 4; mt++)
                #pragma unroll
                for (int nt = 0; nt < 4; nt++) mma8(acc[mt][nt], af[mt], bf[nt]);
        }
        __syncthreads();
        if (nx) { storeT(); __syncthreads(); }
    }

    #pragma unroll
    for (int mt = 0; mt < 4; mt++)
        #pragma unroll
        for (int nt = 0; nt < 4; nt++) {
            int m = i0 + wm0 + mt * 16 + g, n = j0 + wn0 + nt * 8 + 2 * l;
            *(float2*)(C + (size_t)m * CH + n) =
                make_float2(acc[mt][nt][0], acc[mt][nt][1]);
            *(float2*)(C + (size_t)(m + 8) * CH + n) =
                make_float2(acc[mt][nt][2], acc[mt][nt][3]);
        }
}

// =================================================================================
// Batched depthwise 3-tap conv.
// =================================================================================
__global__ __launch_bounds__(256) void dwconv3(
    const float* __restrict__ x0, const float* __restrict__ x1, const float* __restrict__ x2,
    const float* __restrict__ w0p, const float* __restrict__ w1p, const float* __restrict__ w2p,
    float* __restrict__ y0, float* __restrict__ y1, float* __restrict__ y2) {
    int z = blockIdx.y;
    const float* x = z == 0 ? x0 : (z == 1 ? x1 : x2);
    const float* wgt = z == 0 ? w0p : (z == 1 ? w1p : w2p);
    float* y = z == 0 ? y0 : (z == 1 ? y1 : y2);

    int idx = blockIdx.x * 256 + threadIdx.x;
    int c = idx & (CH - 1);
    int t = idx >> 10;
    float w0 = wgt[c * 3 + 0], w1 = wgt[c * 3 + 1], w2 = wgt[c * 3 + 2];
    float xm = (t > 0)       ? x[idx - CH] : 0.f;
    float xc = x[idx];
    float xp = (t < SEQ - 1) ? x[idx + CH] : 0.f;
    y[idx] = fmaf(w0, xm, fmaf(w1, xc, w2 * xp));
}

// =================================================================================
// qk kernel (TF32), BK=64 x 2 chunks.
//   chunk0: U=q_i[d], V=k_j^T          chunk1: U=relw[d][i], V=q_j^T
//   qk[i,j] = (sum) / 32 + prev[h,i,j]
// =================================================================================
__global__ __launch_bounds__(256) void qk_tf32(
    const float* __restrict__ q, const float* __restrict__ k,
    const float* __restrict__ relw, const float* __restrict__ prev,
    float* __restrict__ out) {
    extern __shared__ unsigned smqk[];
    unsigned (*sU)[68]  = (unsigned(*)[68])smqk;                // [128][68] i-major
    unsigned (*sV)[136] = (unsigned(*)[136])(smqk + 128 * 68);  // [64][136] k-major

    const int h = blockIdx.z, i0 = blockIdx.y * 128, j0 = blockIdx.x * 128;
    const int tid = threadIdx.x, lane = tid & 31, wid = tid >> 5;
    const int g = lane >> 2, l = lane & 3;
    const int wm0 = (wid >> 2) * 64, wn0 = (wid & 3) * 32;

    float acc[4][4][4] = {};

    #pragma unroll
    for (int ch = 0; ch < 2; ch++) {
        if (ch == 0) {
            #pragma unroll
            for (int n = 0; n < 8; n++) {       // U = q_i
                int f = tid + n * 256, i = f >> 4, d = (f & 15) * 4;
                float4 t = *(const float4*)(q + (size_t)(i0 + i) * CH + h * DH + d);
                sU[i][d] = f2t(t.x); sU[i][d + 1] = f2t(t.y);
                sU[i][d + 2] = f2t(t.z); sU[i][d + 3] = f2t(t.w);
            }
            #pragma unroll
            for (int n = 0; n < 8; n++) {       // V = k_j^T
                int f = tid + n * 256, j = f >> 4, d = (f & 15) * 4;
                float4 t = *(const float4*)(k + (size_t)(j0 + j) * CH + h * DH + d);
                sV[d][j] = f2t(t.x); sV[d + 1][j] = f2t(t.y);
                sV[d + 2][j] = f2t(t.z); sV[d + 3][j] = f2t(t.w);
            }
        } else {
            #pragma unroll
            for (int n = 0; n < 8; n++) {       // U = relw[d][i]
                int f = tid + n * 256, dd = f >> 5, i4 = (f & 31) * 4;
                float4 t = *(const float4*)(relw + (size_t)dd * CROP + i0 + i4);
                sU[i4][dd] = f2t(t.x); sU[i4 + 1][dd] = f2t(t.y);
                sU[i4 + 2][dd] = f2t(t.z); sU[i4 + 3][dd] = f2t(t.w);
            }
            #pragma unroll
            for (int n = 0; n < 8; n++) {       // V = q_j^T
                int f = tid + n * 256, j = f >> 4, d = (f & 15) * 4;
                float4 t = *(const float4*)(q + (size_t)(j0 + j) * CH + h * DH + d);
                sV[d][j] = f2t(t.x); sV[d + 1][j] = f2t(t.y);
                sV[d + 2][j] = f2t(t.z); sV[d + 3][j] = f2t(t.w);
            }
        }
        __syncthreads();
        #pragma unroll
        for (int ks = 0; ks < 8; ks++) {
            int kk = ks * 8;
            unsigned af[4][4], bf[4][2];
            #pragma unroll
            for (int mt = 0; mt < 4; mt++) {
                int m = wm0 + mt * 16 + g;
                af[mt][0] = sU[m][kk + l];       af[mt][1] = sU[m + 8][kk + l];
                af[mt][2] = sU[m][kk + 4 + l];   af[mt][3] = sU[m + 8][kk + 4 + l];
            }
            #pragma unroll
            for (int nt = 0; nt < 4; nt++) {
                int n = wn0 + nt * 8 + g;
                bf[nt][0] = sV[kk + l][n];       bf[nt][1] = sV[kk + 4 + l][n];
            }
            #pragma unroll
            for (int mt = 0; mt < 4; mt++)
                #pragma unroll
                for (int nt = 0; nt < 4; nt++) mma8(acc[mt][nt], af[mt], bf[nt]);
        }
        __syncthreads();
    }

    const float scale = 0.03125f;   // 1/sqrt(1024)
    #pragma unroll
    for (int mt = 0; mt < 4; mt++)
        #pragma unroll
        for (int nt = 0; nt < 4; nt++) {
            int m = i0 + wm0 + mt * 16 + g, n = j0 + wn0 + nt * 8 + 2 * l;
            size_t o0 = ((size_t)h * SEQ + m) * SEQ + n;
            size_t o1 = o0 + (size_t)8 * SEQ;
            float2 p0 = *(const float2*)(prev + o0);
            float2 p1 = *(const float2*)(prev + o1);
            *(float2*)(out + o0) = make_float2(fmaf(acc[mt][nt][0], scale, p0.x),
                                               fmaf(acc[mt][nt][1], scale, p0.y));
            *(float2*)(out + o1) = make_float2(fmaf(acc[mt][nt][2], scale, p1.x),
                                               fmaf(acc[mt][nt][3], scale, p1.y));
        }
}

// =================================================================================
// Fused softmax + A@V, single pass (no max subtraction: qk values are O(1);
// softmax is shift-invariant so result is identical after normalization).
// Grid: (SEQ/64, NB) = 512 blocks, 256 threads, ~71KB smem -> ~3 blocks/SM.
// =================================================================================
__global__ __launch_bounds__(256) void fused_sm_av(const float* __restrict__ qk,
                                                   const float* __restrict__ v,
                                                   float* __restrict__ o) {
    extern __shared__ char smraw[];
    unsigned* sP = (unsigned*)smraw;                                 // [64][132] tf32 P
    unsigned (*sV)[72] = (unsigned(*)[72])(smraw + 64 * 132 * 4);    // [128][72] tf32 V
    float* sm_inv = (float*)(smraw + 64 * 132 * 4 + 128 * 72 * 4);   // [64]

    const int h = blockIdx.y, i0 = blockIdx.x * 64;
    const int tid = threadIdx.x, lane = tid & 31, wid = tid >> 5;
    const int g = lane >> 2, l = lane & 3;
    // 8 warps: 4 m16-tiles (wid>>1), 2 n-halves of DH (wid&1)
    const int wm0 = (wid >> 1) * 16, wn0 = (wid & 1) * 32;

    const float* qkh = qk + ((size_t)h * SEQ + i0) * SEQ;
    const int rr = tid >> 2;            // row 0..63 (4 threads per row)
    const int cb = (tid & 3) * 32;      // 32-col chunk within the 128-col tile

    float acc[4][4] = {};
    float lsum = 0.f;

    for (int jt = 0; jt < 16; jt++) {
        const int j0 = jt * 128;
        // qk tile: 8 float4 per thread, exp, sum, store tf32
        const float* rowp = qkh + (size_t)rr * SEQ + j0 + cb;
        #pragma unroll
        for (int jj = 0; jj < 8; jj++) {
            float4 t = *(const float4*)(rowp + jj * 4);
            float e0 = __expf(t.x), e1 = __expf(t.y);
            float e2 = __expf(t.z), e3 = __expf(t.w);
            lsum += (e0 + e1) + (e2 + e3);
            *(uint4*)&sP[rr * 132 + cb + jj * 4] =
                make_uint4(f2t(e0), f2t(e1), f2t(e2), f2t(e3));
        }
        // V tile: 128 x 64
        #pragma unroll
        for (int n = 0; n < 8; n++) {
            int f = tid + n * 256, r = f >> 4, c4 = (f & 15) * 4;
            float4 t = *(const float4*)(v + (size_t)(j0 + r) * CH + h * DH + c4);
            sV[r][c4] = f2t(t.x); sV[r][c4 + 1] = f2t(t.y);
            sV[r][c4 + 2] = f2t(t.z); sV[r][c4 + 3] = f2t(t.w);
        }
        __syncthreads();

        #pragma unroll
        for (int ks = 0; ks < 16; ks++) {
            int kk = ks * 8;
            unsigned af[4], bf[4][2];
            int m = wm0 + g;
            af[0] = sP[m * 132 + kk + l];
            af[1] = sP[(m + 8) * 132 + kk + l];
            af[2] = sP[m * 132 + kk + 4 + l];
            af[3] = sP[(m + 8) * 132 + kk + 4 + l];
            #pragma unroll
            for (int nt = 0; nt < 4; nt++) {
                int n = wn0 + nt * 8 + g;
                bf[nt][0] = sV[kk + l][n];   bf[nt][1] = sV[kk + 4 + l][n];
            }
            #pragma unroll
            for (int nt = 0; nt < 4; nt++) mma8(acc[nt], af, bf[nt]);
        }
        __syncthreads();
    }

    // reduce row sums over the 4 threads per row (quad-aligned lanes)
    lsum += __shfl_xor_sync(~0u, lsum, 1);
    lsum += __shfl_xor_sync(~0u, lsum, 2);
    if ((tid & 3) == 0) sm_inv[rr] = 1.0f / lsum;
    __syncthreads();

    // normalize + store
    {
        int m = wm0 + g;
        float inv0 = sm_inv[m], inv1 = sm_inv[m + 8];
        #pragma unroll
        for (int nt = 0; nt < 4; nt++) {
            int n = wn0 + nt * 8 + 2 * l;
            *(float2*)(o + (size_t)(i0 + m) * CH + h * DH + n) =
                make_float2(acc[nt][0] * inv0, acc[nt][1] * inv0);
            *(float2*)(o + (size_t)(i0 + m + 8) * CH + h * DH + n) =
                make_float2(acc[nt][2] * inv1, acc[nt][3] * inv1);
        }
    }
}

// =================================================================================
extern "C" void kernel_launch(void* const* d_in, const int* in_sizes, int n_in,
                              void* d_out, int out_size) {
    const float* x    = (const float*)d_in[0];
    const float* prev = (const float*)d_in[1];
    const float* Wq   = (const float*)d_in[2];
    const float* Wk   = (const float*)d_in[3];
    const float* Wv   = (const float*)d_in[4];
    const float* Wo   = (const float*)d_in[5];
    const float* cq   = (const float*)d_in[6];
    const float* ck   = (const float*)d_in[7];
    const float* cv   = (const float*)d_in[8];
    const float* relw = (const float*)d_in[9];

    float* out0 = (float*)d_out;

    float *xq, *xk, *xv, *q, *k, *v, *o, *qks;
    cudaGetSymbolAddress((void**)&xq, g_xq);
    cudaGetSymbolAddress((void**)&xk, g_xk);
    cudaGetSymbolAddress((void**)&xv, g_xv);
    cudaGetSymbolAddress((void**)&q,  g_q);
    cudaGetSymbolAddress((void**)&k,  g_k);
    cudaGetSymbolAddress((void**)&v,  g_v);
    cudaGetSymbolAddress((void**)&o,  g_o);
    cudaGetSymbolAddress((void**)&qks, g_qk);

    const long long need = (long long)SEQ * CH + (long long)NB * SEQ * SEQ;
    float* qk_dst = ((long long)out_size >= need) ? (out0 + (size_t)SEQ * CH) : qks;

    const int SMEM_QK = (128 * 68 + 64 * 136) * (int)sizeof(unsigned);           // 69632
    const int SMEM_F  = (64 * 132 + 128 * 72 + 64) * (int)sizeof(float);          // 71168
    cudaFuncSetAttribute(qk_tf32, cudaFuncAttributeMaxDynamicSharedMemorySize, SMEM_QK);
    cudaFuncSetAttribute(fused_sm_av, cudaFuncAttributeMaxDynamicSharedMemorySize, SMEM_F);

    gemm_xw<<<dim3(CH / 128, SEQ / 128, 3), 256>>>(x, Wq, Wk, Wv, xq, xk, xv);

    dwconv3<<<dim3(SEQ * CH / 256, 3), 256>>>(xq, xk, xv, cq, ck, cv, q, k, v);

    qk_tf32<<<dim3(SEQ / 128, SEQ / 128, NB), 256, SMEM_QK>>>(q, k, relw, prev, qk_dst);

    fused_sm_av<<<dim3(SEQ / 64, NB), 256, SMEM_F>>>(qk_dst, v, o);

    gemm_xw<<<dim3(CH / 128, SEQ / 128, 1), 256>>>(o, Wo, Wo, Wo, out0, out0, out0);
}

// round 8
// speedup vs baseline: 1.2441x; 1.2441x over previous
#include <cuda_runtime.h>
#include <math.h>

constexpr int SEQ  = 2048;
constexpr int CH   = 1024;
constexpr int NB   = 16;
constexpr int DH   = 64;
constexpr int CROP = 2048;

// ---------------- scratch ----------------
__device__ float g_xq[SEQ * CH];
__device__ float g_xk[SEQ * CH];
__device__ float g_xv[SEQ * CH];
__device__ float g_q [SEQ * CH];
__device__ float g_k [SEQ * CH];
__device__ float g_v [SEQ * CH];
__device__ float g_o [SEQ * CH];
__device__ float g_e [(size_t)NB * SEQ * SEQ];   // exp(qk), unnormalized
__device__ float g_ps[(size_t)NB * 16 * SEQ];    // partial row sums per j-tile (2MB)
__device__ float g_qk[(size_t)NB * SEQ * SEQ];   // fallback if out buffer too small

// ---------------- tf32 helpers ----------------
__device__ __forceinline__ unsigned f2t(float f) {
    unsigned u; asm("cvt.rna.tf32.f32 %0, %1;" : "=r"(u) : "f"(f)); return u;
}
__device__ __forceinline__ void mma8(float c[4], const unsigned a[4], const unsigned b[2]) {
    asm volatile(
        "mma.sync.aligned.m16n8k8.row.col.f32.tf32.tf32.f32 "
        "{%0,%1,%2,%3},{%4,%5,%6,%7},{%8,%9},{%0,%1,%2,%3};"
        : "+f"(c[0]), "+f"(c[1]), "+f"(c[2]), "+f"(c[3])
        : "r"(a[0]), "r"(a[1]), "r"(a[2]), "r"(a[3]), "r"(b[0]), "r"(b[1]));
}

// =================================================================================
// Batched TF32 GEMM: C[z] = A @ B[z], A:[2048x1024], B:[1024x1024] row-major.
// =================================================================================
__global__ __launch_bounds__(256) void gemm_xw(
    const float* __restrict__ A,
    const float* __restrict__ B0, const float* __restrict__ B1, const float* __restrict__ B2,
    float* __restrict__ C0, float* __restrict__ C1, float* __restrict__ C2) {
    __shared__ unsigned sA[128][36];
    __shared__ unsigned sB[32][136];

    const float* B = blockIdx.z == 0 ? B0 : (blockIdx.z == 1 ? B1 : B2);
    float*       C = blockIdx.z == 0 ? C0 : (blockIdx.z == 1 ? C1 : C2);

    const int tid = threadIdx.x, lane = tid & 31, wid = tid >> 5;
    const int i0 = blockIdx.y * 128, j0 = blockIdx.x * 128;
    const int wm0 = (wid >> 2) * 64, wn0 = (wid & 3) * 32;
    const int g = lane >> 2, l = lane & 3;

    float4 pa[4], pb[4];

    auto loadT = [&](int k0) {
        #pragma unroll
        for (int n = 0; n < 4; n++) {
            int f = tid + n * 256, r = f >> 3, c = (f & 7) * 4;
            pa[n] = *(const float4*)(A + (size_t)(i0 + r) * CH + k0 + c);
        }
        #pragma unroll
        for (int n = 0; n < 4; n++) {
            int f = tid + n * 256, r = f >> 5, c = (f & 31) * 4;
            pb[n] = *(const float4*)(B + (size_t)(k0 + r) * CH + j0 + c);
        }
    };
    auto storeT = [&]() {
        #pragma unroll
        for (int n = 0; n < 4; n++) {
            int f = tid + n * 256, r = f >> 3, c = (f & 7) * 4;
            sA[r][c] = f2t(pa[n].x); sA[r][c + 1] = f2t(pa[n].y);
            sA[r][c + 2] = f2t(pa[n].z); sA[r][c + 3] = f2t(pa[n].w);
        }
        #pragma unroll
        for (int n = 0; n < 4; n++) {
            int f = tid + n * 256, r = f >> 5, c = (f & 31) * 4;
            sB[r][c] = f2t(pb[n].x); sB[r][c + 1] = f2t(pb[n].y);
            sB[r][c + 2] = f2t(pb[n].z); sB[r][c + 3] = f2t(pb[n].w);
        }
    };

    float acc[4][4][4] = {};
    loadT(0); storeT(); __syncthreads();

    for (int k0 = 0; k0 < CH; k0 += 32) {
        bool nx = (k0 + 32) < CH;
        if (nx) loadT(k0 + 32);
        #pragma unroll
        for (int ks = 0; ks < 4; ks++) {
            int kk = ks * 8;
            unsigned af[4][4], bf[4][2];
            #pragma unroll
            for (int mt = 0; mt < 4; mt++) {
                int m = wm0 + mt * 16 + g;
                af[mt][0] = sA[m][kk + l];       af[mt][1] = sA[m + 8][kk + l];
                af[mt][2] = sA[m][kk + 4 + l];   af[mt][3] = sA[m + 8][kk + 4 + l];
            }
            #pragma unroll
            for (int nt = 0; nt < 4; nt++) {
                int n = wn0 + nt * 8 + g;
                bf[nt][0] = sB[kk + l][n];       bf[nt][1] = sB[kk + 4 + l][n];
            }
            #pragma unroll
            for (int mt = 0; mt < 4; mt++)
                #pragma unroll
                for (int nt = 0; nt < 4; nt++) mma8(acc[mt][nt], af[mt], bf[nt]);
        }
        __syncthreads();
        if (nx) { storeT(); __syncthreads(); }
    }

    #pragma unroll
    for (int mt = 0; mt < 4; mt++)
        #pragma unroll
        for (int nt = 0; nt < 4; nt++) {
            int m = i0 + wm0 + mt * 16 + g, n = j0 + wn0 + nt * 8 + 2 * l;
            *(float2*)(C + (size_t)m * CH + n) =
                make_float2(acc[mt][nt][0], acc[mt][nt][1]);
            *(float2*)(C + (size_t)(m + 8) * CH + n) =
                make_float2(acc[mt][nt][2], acc[mt][nt][3]);
        }
}

// =================================================================================
// Batched depthwise 3-tap conv.
// =================================================================================
__global__ __launch_bounds__(256) void dwconv3(
    const float* __restrict__ x0, const float* __restrict__ x1, const float* __restrict__ x2,
    const float* __restrict__ w0p, const float* __restrict__ w1p, const float* __restrict__ w2p,
    float* __restrict__ y0, float* __restrict__ y1, float* __restrict__ y2) {
    int z = blockIdx.y;
    const float* x = z == 0 ? x0 : (z == 1 ? x1 : x2);
    const float* wgt = z == 0 ? w0p : (z == 1 ? w1p : w2p);
    float* y = z == 0 ? y0 : (z == 1 ? y1 : y2);

    int idx = blockIdx.x * 256 + threadIdx.x;
    int c = idx & (CH - 1);
    int t = idx >> 10;
    float w0 = wgt[c * 3 + 0], w1 = wgt[c * 3 + 1], w2 = wgt[c * 3 + 2];
    float xm = (t > 0)       ? x[idx - CH] : 0.f;
    float xc = x[idx];
    float xp = (t < SEQ - 1) ? x[idx + CH] : 0.f;
    y[idx] = fmaf(w0, xm, fmaf(w1, xc, w2 * xp));
}

// =================================================================================
// qk kernel (TF32), BK=64 x 2 chunks. Epilogue additionally:
//   - writes E = exp(qk) to g_e
//   - writes deterministic per-(row, j-tile) partial sums of E to g_ps
// Grid: (j-tile, i-tile, h).
// =================================================================================
__global__ __launch_bounds__(256) void qk_tf32(
    const float* __restrict__ q, const float* __restrict__ k,
    const float* __restrict__ relw, const float* __restrict__ prev,
    float* __restrict__ out, float* __restrict__ eout, float* __restrict__ psum) {
    extern __shared__ unsigned smqk[];
    unsigned (*sU)[68]  = (unsigned(*)[68])smqk;                // [128][68] i-major
    unsigned (*sV)[136] = (unsigned(*)[136])(smqk + 128 * 68);  // [64][136] k-major

    const int h = blockIdx.z, i0 = blockIdx.y * 128, j0 = blockIdx.x * 128;
    const int tid = threadIdx.x, lane = tid & 31, wid = tid >> 5;
    const int g = lane >> 2, l = lane & 3;
    const int wm0 = (wid >> 2) * 64, wn0 = (wid & 3) * 32;

    float acc[4][4][4] = {};

    #pragma unroll
    for (int ch = 0; ch < 2; ch++) {
        if (ch == 0) {
            #pragma unroll
            for (int n = 0; n < 8; n++) {       // U = q_i
                int f = tid + n * 256, i = f >> 4, d = (f & 15) * 4;
                float4 t = *(const float4*)(q + (size_t)(i0 + i) * CH + h * DH + d);
                sU[i][d] = f2t(t.x); sU[i][d + 1] = f2t(t.y);
                sU[i][d + 2] = f2t(t.z); sU[i][d + 3] = f2t(t.w);
            }
            #pragma unroll
            for (int n = 0; n < 8; n++) {       // V = k_j^T
                int f = tid + n * 256, j = f >> 4, d = (f & 15) * 4;
                float4 t = *(const float4*)(k + (size_t)(j0 + j) * CH + h * DH + d);
                sV[d][j] = f2t(t.x); sV[d + 1][j] = f2t(t.y);
                sV[d + 2][j] = f2t(t.z); sV[d + 3][j] = f2t(t.w);
            }
        } else {
            #pragma unroll
            for (int n = 0; n < 8; n++) {       // U = relw[d][i]
                int f = tid + n * 256, dd = f >> 5, i4 = (f & 31) * 4;
                float4 t = *(const float4*)(relw + (size_t)dd * CROP + i0 + i4);
                sU[i4][dd] = f2t(t.x); sU[i4 + 1][dd] = f2t(t.y);
                sU[i4 + 2][dd] = f2t(t.z); sU[i4 + 3][dd] = f2t(t.w);
            }
            #pragma unroll
            for (int n = 0; n < 8; n++) {       // V = q_j^T
                int f = tid + n * 256, j = f >> 4, d = (f & 15) * 4;
                float4 t = *(const float4*)(q + (size_t)(j0 + j) * CH + h * DH + d);
                sV[d][j] = f2t(t.x); sV[d + 1][j] = f2t(t.y);
                sV[d + 2][j] = f2t(t.z); sV[d + 3][j] = f2t(t.w);
            }
        }
        __syncthreads();
        #pragma unroll
        for (int ks = 0; ks < 8; ks++) {
            int kk = ks * 8;
            unsigned af[4][4], bf[4][2];
            #pragma unroll
            for (int mt = 0; mt < 4; mt++) {
                int m = wm0 + mt * 16 + g;
                af[mt][0] = sU[m][kk + l];       af[mt][1] = sU[m + 8][kk + l];
                af[mt][2] = sU[m][kk + 4 + l];   af[mt][3] = sU[m + 8][kk + 4 + l];
            }
            #pragma unroll
            for (int nt = 0; nt < 4; nt++) {
                int n = wn0 + nt * 8 + g;
                bf[nt][0] = sV[kk + l][n];       bf[nt][1] = sV[kk + 4 + l][n];
            }
            #pragma unroll
            for (int mt = 0; mt < 4; mt++)
                #pragma unroll
                for (int nt = 0; nt < 4; nt++) mma8(acc[mt][nt], af[mt], bf[nt]);
        }
        __syncthreads();
    }
    // sU/sV no longer needed; alias the front of smem for partial-sum staging.
    float* psm = (float*)smqk;   // [128][4]

    const float scale = 0.03125f;   // 1/sqrt(1024)
    float rs0[4] = {0.f, 0.f, 0.f, 0.f};   // per mt: row (wm0+mt*16+g)
    float rs1[4] = {0.f, 0.f, 0.f, 0.f};   // per mt: row (wm0+mt*16+g+8)
    #pragma unroll
    for (int mt = 0; mt < 4; mt++)
        #pragma unroll
        for (int nt = 0; nt < 4; nt++) {
            int m = i0 + wm0 + mt * 16 + g, n = j0 + wn0 + nt * 8 + 2 * l;
            size_t o0 = ((size_t)h * SEQ + m) * SEQ + n;
            size_t o1 = o0 + (size_t)8 * SEQ;
            float2 p0 = *(const float2*)(prev + o0);
            float2 p1 = *(const float2*)(prev + o1);
            float v0 = fmaf(acc[mt][nt][0], scale, p0.x);
            float v1 = fmaf(acc[mt][nt][1], scale, p0.y);
            float v2 = fmaf(acc[mt][nt][2], scale, p1.x);
            float v3 = fmaf(acc[mt][nt][3], scale, p1.y);
            *(float2*)(out + o0) = make_float2(v0, v1);
            *(float2*)(out + o1) = make_float2(v2, v3);
            float e0 = __expf(v0), e1 = __expf(v1);
            float e2 = __expf(v2), e3 = __expf(v3);
            *(float2*)(eout + o0) = make_float2(e0, e1);
            *(float2*)(eout + o1) = make_float2(e2, e3);
            rs0[mt] += e0 + e1;
            rs1[mt] += e2 + e3;
        }

    // reduce over the 4 lanes (l) sharing each row, then over the 4 j-warps via smem
    #pragma unroll
    for (int mt = 0; mt < 4; mt++) {
        rs0[mt] += __shfl_xor_sync(~0u, rs0[mt], 1);
        rs0[mt] += __shfl_xor_sync(~0u, rs0[mt], 2);
        rs1[mt] += __shfl_xor_sync(~0u, rs1[mt], 1);
        rs1[mt] += __shfl_xor_sync(~0u, rs1[mt], 2);
    }
    if (l == 0) {
        #pragma unroll
        for (int mt = 0; mt < 4; mt++) {
            psm[(wm0 + mt * 16 + g) * 4 + (wid & 3)]     = rs0[mt];
            psm[(wm0 + mt * 16 + g + 8) * 4 + (wid & 3)] = rs1[mt];
        }
    }
    __syncthreads();
    if (tid < 128) {
        float s = psm[tid * 4] + psm[tid * 4 + 1] + psm[tid * 4 + 2] + psm[tid * 4 + 3];
        psum[((size_t)h * 16 + blockIdx.x) * SEQ + i0 + tid] = s;
    }
}

// =================================================================================
// AV kernel (TF32): O[i, h*64+d] = (1/s_i) * sum_j E[h,i,j] * v[j, h*64+d]
// Row sums reconstructed deterministically from g_ps partials.
// =================================================================================
__global__ __launch_bounds__(256) void av_tf32(const float* __restrict__ E,
                                               const float* __restrict__ v,
                                               const float* __restrict__ psum,
                                               float* __restrict__ o) {
    __shared__ unsigned sA[128][36];   // [i][k]
    __shared__ unsigned sB[32][72];    // [k][d]
    __shared__ float s_inv[128];
    const int h = blockIdx.y, i0 = blockIdx.x * 128;
    const float* Ah = E + (size_t)h * SEQ * SEQ;
    const int tid = threadIdx.x, lane = tid & 31, wid = tid >> 5;
    const int g = lane >> 2, l = lane & 3;
    const int wm0 = (wid >> 1) * 32, wn0 = (wid & 1) * 32;

    // row sums from partials
    for (int r = tid; r < 128; r += 256) {
        float s = 0.f;
        #pragma unroll
        for (int jt = 0; jt < 16; jt++)
            s += psum[((size_t)h * 16 + jt) * SEQ + i0 + r];
        s_inv[r] = 1.0f / s;
    }

    float4 pa[4], pb[2];
    auto loadT = [&](int k0) {
        #pragma unroll
        for (int n = 0; n < 4; n++) {
            int f = tid + n * 256, r = f >> 3, c = (f & 7) * 4;
            pa[n] = *(const float4*)(Ah + (size_t)(i0 + r) * SEQ + k0 + c);
        }
        #pragma unroll
        for (int n = 0; n < 2; n++) {
            int f = tid + n * 256, rr = f >> 4, cc = (f & 15) * 4;
            pb[n] = *(const float4*)(v + (size_t)(k0 + rr) * CH + h * DH + cc);
        }
    };
    auto storeT = [&]() {
        #pragma unroll
        for (int n = 0; n < 4; n++) {
            int f = tid + n * 256, r = f >> 3, c = (f & 7) * 4;
            sA[r][c] = f2t(pa[n].x); sA[r][c + 1] = f2t(pa[n].y);
            sA[r][c + 2] = f2t(pa[n].z); sA[r][c + 3] = f2t(pa[n].w);
        }
        #pragma unroll
        for (int n = 0; n < 2; n++) {
            int f = tid + n * 256, rr = f >> 4, cc = (f & 15) * 4;
            sB[rr][cc] = f2t(pb[n].x); sB[rr][cc + 1] = f2t(pb[n].y);
            sB[rr][cc + 2] = f2t(pb[n].z); sB[rr][cc + 3] = f2t(pb[n].w);
        }
    };

    float acc[2][4][4] = {};
    loadT(0); storeT(); __syncthreads();

    for (int k0 = 0; k0 < SEQ; k0 += 32) {
        bool nx = (k0 + 32) < SEQ;
        if (nx) loadT(k0 + 32);
        #pragma unroll
        for (int ks = 0; ks < 4; ks++) {
            int kk = ks * 8;
            unsigned af[2][4], bf[4][2];
            #pragma unroll
            for (int mt = 0; mt < 2; mt++) {
                int m = wm0 + mt * 16 + g;
                af[mt][0] = sA[m][kk + l];       af[mt][1] = sA[m + 8][kk + l];
                af[mt][2] = sA[m][kk + 4 + l];   af[mt][3] = sA[m + 8][kk + 4 + l];
            }
            #pragma unroll
            for (int nt = 0; nt < 4; nt++) {
                int n = wn0 + nt * 8 + g;
                bf[nt][0] = sB[kk + l][n];       bf[nt][1] = sB[kk + 4 + l][n];
            }
            #pragma unroll
            for (int mt = 0; mt < 2; mt++)
                #pragma unroll
                for (int nt = 0; nt < 4; nt++) mma8(acc[mt][nt], af[mt], bf[nt]);
        }
        __syncthreads();
        if (nx) { storeT(); __syncthreads(); }
    }

    #pragma unroll
    for (int mt = 0; mt < 2; mt++) {
        int mloc = wm0 + mt * 16 + g;
        float inv0 = s_inv[mloc], inv1 = s_inv[mloc + 8];
        #pragma unroll
        for (int nt = 0; nt < 4; nt++) {
            int n = wn0 + nt * 8 + 2 * l;
            *(float2*)(o + (size_t)(i0 + mloc) * CH + h * DH + n) =
                make_float2(acc[mt][nt][0] * inv0, acc[mt][nt][1] * inv0);
            *(float2*)(o + (size_t)(i0 + mloc + 8) * CH + h * DH + n) =
                make_float2(acc[mt][nt][2] * inv1, acc[mt][nt][3] * inv1);
        }
    }
}

// =================================================================================
extern "C" void kernel_launch(void* const* d_in, const int* in_sizes, int n_in,
                              void* d_out, int out_size) {
    const float* x    = (const float*)d_in[0];
    const float* prev = (const float*)d_in[1];
    const float* Wq   = (const float*)d_in[2];
    const float* Wk   = (const float*)d_in[3];
    const float* Wv   = (const float*)d_in[4];
    const float* Wo   = (const float*)d_in[5];
    const float* cq   = (const float*)d_in[6];
    const float* ck   = (const float*)d_in[7];
    const float* cv   = (const float*)d_in[8];
    const float* relw = (const float*)d_in[9];

    float* out0 = (float*)d_out;

    float *xq, *xk, *xv, *q, *k, *v, *o, *e, *ps, *qks;
    cudaGetSymbolAddress((void**)&xq, g_xq);
    cudaGetSymbolAddress((void**)&xk, g_xk);
    cudaGetSymbolAddress((void**)&xv, g_xv);
    cudaGetSymbolAddress((void**)&q,  g_q);
    cudaGetSymbolAddress((void**)&k,  g_k);
    cudaGetSymbolAddress((void**)&v,  g_v);
    cudaGetSymbolAddress((void**)&o,  g_o);
    cudaGetSymbolAddress((void**)&e,  g_e);
    cudaGetSymbolAddress((void**)&ps, g_ps);
    cudaGetSymbolAddress((void**)&qks, g_qk);

    const long long need = (long long)SEQ * CH + (long long)NB * SEQ * SEQ;
    float* qk_dst = ((long long)out_size >= need) ? (out0 + (size_t)SEQ * CH) : qks;

    const int SMEM_QK = (128 * 68 + 64 * 136) * (int)sizeof(unsigned);   // 69632
    cudaFuncSetAttribute(qk_tf32, cudaFuncAttributeMaxDynamicSharedMemorySize, SMEM_QK);

    gemm_xw<<<dim3(CH / 128, SEQ / 128, 3), 256>>>(x, Wq, Wk, Wv, xq, xk, xv);

    dwconv3<<<dim3(SEQ * CH / 256, 3), 256>>>(xq, xk, xv, cq, ck, cv, q, k, v);

    qk_tf32<<<dim3(SEQ / 128, SEQ / 128, NB), 256, SMEM_QK>>>(q, k, relw, prev,
                                                              qk_dst, e, ps);

    av_tf32<<<dim3(SEQ / 128, NB), 256>>>(e, v, ps, o);

    gemm_xw<<<dim3(CH / 128, SEQ / 128, 1), 256>>>(o, Wo, Wo, Wo, out0, out0, out0);
}

// round 9
// speedup vs baseline: 1.2900x; 1.0369x over previous
#include <cuda_runtime.h>
#include <math.h>

constexpr int SEQ  = 2048;
constexpr int CH   = 1024;
constexpr int NB   = 16;
constexpr int DH   = 64;
constexpr int CROP = 2048;

// ---------------- scratch ----------------
__device__ float g_xq[SEQ * CH];
__device__ float g_xk[SEQ * CH];
__device__ float g_xv[SEQ * CH];
__device__ float g_q [SEQ * CH];
__device__ float g_k [SEQ * CH];
__device__ float g_v [SEQ * CH];
__device__ float g_o [SEQ * CH];
__device__ float g_qk[(size_t)NB * SEQ * SEQ];   // fallback if out buffer too small

// ---------------- tf32 helpers ----------------
__device__ __forceinline__ unsigned f2t(float f) {
    unsigned u; asm("cvt.rna.tf32.f32 %0, %1;" : "=r"(u) : "f"(f)); return u;
}
__device__ __forceinline__ void mma8(float c[4], const unsigned a[4], const unsigned b[2]) {
    asm volatile(
        "mma.sync.aligned.m16n8k8.row.col.f32.tf32.tf32.f32 "
        "{%0,%1,%2,%3},{%4,%5,%6,%7},{%8,%9},{%0,%1,%2,%3};"
        : "+f"(c[0]), "+f"(c[1]), "+f"(c[2]), "+f"(c[3])
        : "r"(a[0]), "r"(a[1]), "r"(a[2]), "r"(a[3]), "r"(b[0]), "r"(b[1]));
}

// =================================================================================
// Batched TF32 GEMM: C[z] = A @ B[z], A:[2048x1024], B:[1024x1024] row-major.
// =================================================================================
__global__ __launch_bounds__(256) void gemm_xw(
    const float* __restrict__ A,
    const float* __restrict__ B0, const float* __restrict__ B1, const float* __restrict__ B2,
    float* __restrict__ C0, float* __restrict__ C1, float* __restrict__ C2) {
    __shared__ unsigned sA[128][36];
    __shared__ unsigned sB[32][136];

    const float* B = blockIdx.z == 0 ? B0 : (blockIdx.z == 1 ? B1 : B2);
    float*       C = blockIdx.z == 0 ? C0 : (blockIdx.z == 1 ? C1 : C2);

    const int tid = threadIdx.x, lane = tid & 31, wid = tid >> 5;
    const int i0 = blockIdx.y * 128, j0 = blockIdx.x * 128;
    const int wm0 = (wid >> 2) * 64, wn0 = (wid & 3) * 32;
    const int g = lane >> 2, l = lane & 3;

    float4 pa[4], pb[4];

    auto loadT = [&](int k0) {
        #pragma unroll
        for (int n = 0; n < 4; n++) {
            int f = tid + n * 256, r = f >> 3, c = (f & 7) * 4;
            pa[n] = *(const float4*)(A + (size_t)(i0 + r) * CH + k0 + c);
        }
        #pragma unroll
        for (int n = 0; n < 4; n++) {
            int f = tid + n * 256, r = f >> 5, c = (f & 31) * 4;
            pb[n] = *(const float4*)(B + (size_t)(k0 + r) * CH + j0 + c);
        }
    };
    auto storeT = [&]() {
        #pragma unroll
        for (int n = 0; n < 4; n++) {
            int f = tid + n * 256, r = f >> 3, c = (f & 7) * 4;
            sA[r][c] = f2t(pa[n].x); sA[r][c + 1] = f2t(pa[n].y);
            sA[r][c + 2] = f2t(pa[n].z); sA[r][c + 3] = f2t(pa[n].w);
        }
        #pragma unroll
        for (int n = 0; n < 4; n++) {
            int f = tid + n * 256, r = f >> 5, c = (f & 31) * 4;
            sB[r][c] = f2t(pb[n].x); sB[r][c + 1] = f2t(pb[n].y);
            sB[r][c + 2] = f2t(pb[n].z); sB[r][c + 3] = f2t(pb[n].w);
        }
    };

    float acc[4][4][4] = {};
    loadT(0); storeT(); __syncthreads();

    for (int k0 = 0; k0 < CH; k0 += 32) {
        bool nx = (k0 + 32) < CH;
        if (nx) loadT(k0 + 32);
        #pragma unroll
        for (int ks = 0; ks < 4; ks++) {
            int kk = ks * 8;
            unsigned af[4][4], bf[4][2];
            #pragma unroll
            for (int mt = 0; mt < 4; mt++) {
                int m = wm0 + mt * 16 + g;
                af[mt][0] = sA[m][kk + l];       af[mt][1] = sA[m + 8][kk + l];
                af[mt][2] = sA[m][kk + 4 + l];   af[mt][3] = sA[m + 8][kk + 4 + l];
            }
            #pragma unroll
            for (int nt = 0; nt < 4; nt++) {
                int n = wn0 + nt * 8 + g;
                bf[nt][0] = sB[kk + l][n];       bf[nt][1] = sB[kk + 4 + l][n];
            }
            #pragma unroll
            for (int mt = 0; mt < 4; mt++)
                #pragma unroll
                for (int nt = 0; nt < 4; nt++) mma8(acc[mt][nt], af[mt], bf[nt]);
        }
        __syncthreads();
        if (nx) { storeT(); __syncthreads(); }
    }

    #pragma unroll
    for (int mt = 0; mt < 4; mt++)
        #pragma unroll
        for (int nt = 0; nt < 4; nt++) {
            int m = i0 + wm0 + mt * 16 + g, n = j0 + wn0 + nt * 8 + 2 * l;
            *(float2*)(C + (size_t)m * CH + n) =
                make_float2(acc[mt][nt][0], acc[mt][nt][1]);
            *(float2*)(C + (size_t)(m + 8) * CH + n) =
                make_float2(acc[mt][nt][2], acc[mt][nt][3]);
        }
}

// =================================================================================
// Batched depthwise 3-tap conv.
// =================================================================================
__global__ __launch_bounds__(256) void dwconv3(
    const float* __restrict__ x0, const float* __restrict__ x1, const float* __restrict__ x2,
    const float* __restrict__ w0p, const float* __restrict__ w1p, const float* __restrict__ w2p,
    float* __restrict__ y0, float* __restrict__ y1, float* __restrict__ y2) {
    int z = blockIdx.y;
    const float* x = z == 0 ? x0 : (z == 1 ? x1 : x2);
    const float* wgt = z == 0 ? w0p : (z == 1 ? w1p : w2p);
    float* y = z == 0 ? y0 : (z == 1 ? y1 : y2);

    int idx = blockIdx.x * 256 + threadIdx.x;
    int c = idx & (CH - 1);
    int t = idx >> 10;
    float w0 = wgt[c * 3 + 0], w1 = wgt[c * 3 + 1], w2 = wgt[c * 3 + 2];
    float xm = (t > 0)       ? x[idx - CH] : 0.f;
    float xc = x[idx];
    float xp = (t < SEQ - 1) ? x[idx + CH] : 0.f;
    y[idx] = fmaf(w0, xm, fmaf(w1, xc, w2 * xp));
}

// =================================================================================
// qk kernel (TF32), BK=64 x 2 chunks. Writes only the required qk output.
//   chunk0: U=q_i[d], V=k_j^T          chunk1: U=relw[d][i], V=q_j^T
//   qk[i,j] = (sum) / 32 + prev[h,i,j]
// =================================================================================
__global__ __launch_bounds__(256) void qk_tf32(
    const float* __restrict__ q, const float* __restrict__ k,
    const float* __restrict__ relw, const float* __restrict__ prev,
    float* __restrict__ out) {
    extern __shared__ unsigned smqk[];
    unsigned (*sU)[68]  = (unsigned(*)[68])smqk;                // [128][68] i-major
    unsigned (*sV)[136] = (unsigned(*)[136])(smqk + 128 * 68);  // [64][136] k-major

    const int h = blockIdx.z, i0 = blockIdx.y * 128, j0 = blockIdx.x * 128;
    const int tid = threadIdx.x, lane = tid & 31, wid = tid >> 5;
    const int g = lane >> 2, l = lane & 3;
    const int wm0 = (wid >> 2) * 64, wn0 = (wid & 3) * 32;

    float acc[4][4][4] = {};

    #pragma unroll
    for (int ch = 0; ch < 2; ch++) {
        if (ch == 0) {
            #pragma unroll
            for (int n = 0; n < 8; n++) {       // U = q_i
                int f = tid + n * 256, i = f >> 4, d = (f & 15) * 4;
                float4 t = *(const float4*)(q + (size_t)(i0 + i) * CH + h * DH + d);
                sU[i][d] = f2t(t.x); sU[i][d + 1] = f2t(t.y);
                sU[i][d + 2] = f2t(t.z); sU[i][d + 3] = f2t(t.w);
            }
            #pragma unroll
            for (int n = 0; n < 8; n++) {       // V = k_j^T
                int f = tid + n * 256, j = f >> 4, d = (f & 15) * 4;
                float4 t = *(const float4*)(k + (size_t)(j0 + j) * CH + h * DH + d);
                sV[d][j] = f2t(t.x); sV[d + 1][j] = f2t(t.y);
                sV[d + 2][j] = f2t(t.z); sV[d + 3][j] = f2t(t.w);
            }
        } else {
            #pragma unroll
            for (int n = 0; n < 8; n++) {       // U = relw[d][i]
                int f = tid + n * 256, dd = f >> 5, i4 = (f & 31) * 4;
                float4 t = *(const float4*)(relw + (size_t)dd * CROP + i0 + i4);
                sU[i4][dd] = f2t(t.x); sU[i4 + 1][dd] = f2t(t.y);
                sU[i4 + 2][dd] = f2t(t.z); sU[i4 + 3][dd] = f2t(t.w);
            }
            #pragma unroll
            for (int n = 0; n < 8; n++) {       // V = q_j^T
                int f = tid + n * 256, j = f >> 4, d = (f & 15) * 4;
                float4 t = *(const float4*)(q + (size_t)(j0 + j) * CH + h * DH + d);
                sV[d][j] = f2t(t.x); sV[d + 1][j] = f2t(t.y);
                sV[d + 2][j] = f2t(t.z); sV[d + 3][j] = f2t(t.w);
            }
        }
        __syncthreads();
        #pragma unroll
        for (int ks = 0; ks < 8; ks++) {
            int kk = ks * 8;
            unsigned af[4][4], bf[4][2];
            #pragma unroll
            for (int mt = 0; mt < 4; mt++) {
                int m = wm0 + mt * 16 + g;
                af[mt][0] = sU[m][kk + l];       af[mt][1] = sU[m + 8][kk + l];
                af[mt][2] = sU[m][kk + 4 + l];   af[mt][3] = sU[m + 8][kk + 4 + l];
            }
            #pragma unroll
            for (int nt = 0; nt < 4; nt++) {
                int n = wn0 + nt * 8 + g;
                bf[nt][0] = sV[kk + l][n];       bf[nt][1] = sV[kk + 4 + l][n];
            }
            #pragma unroll
            for (int mt = 0; mt < 4; mt++)
                #pragma unroll
                for (int nt = 0; nt < 4; nt++) mma8(acc[mt][nt], af[mt], bf[nt]);
        }
        __syncthreads();
    }

    const float scale = 0.03125f;   // 1/sqrt(1024)
    #pragma unroll
    for (int mt = 0; mt < 4; mt++)
        #pragma unroll
        for (int nt = 0; nt < 4; nt++) {
            int m = i0 + wm0 + mt * 16 + g, n = j0 + wn0 + nt * 8 + 2 * l;
            size_t o0 = ((size_t)h * SEQ + m) * SEQ + n;
            size_t o1 = o0 + (size_t)8 * SEQ;
            float2 p0 = *(const float2*)(prev + o0);
            float2 p1 = *(const float2*)(prev + o1);
            *(float2*)(out + o0) = make_float2(fmaf(acc[mt][nt][0], scale, p0.x),
                                               fmaf(acc[mt][nt][1], scale, p0.y));
            *(float2*)(out + o1) = make_float2(fmaf(acc[mt][nt][2], scale, p1.x),
                                               fmaf(acc[mt][nt][3], scale, p1.y));
        }
}

// =================================================================================
// AV kernel with on-the-fly softmax: reads qk, computes E=exp(qk) while staging
// tiles, accumulates per-row denominators in registers across the full K loop,
// and normalizes in the epilogue. No E matrix, no partial-sum array.
//   O[i, h*64+d] = (1/s_i) * sum_j exp(qk[h,i,j]) * v[j, h*64+d]
// =================================================================================
__global__ __launch_bounds__(256) void av_tf32(const float* __restrict__ qk,
                                               const float* __restrict__ v,
                                               float* __restrict__ o) {
    __shared__ unsigned sA[128][36];   // [i][k] tf32 exp(qk)
    __shared__ unsigned sB[32][72];    // [k][d] tf32 v
    __shared__ float s_sum[128];
    const int h = blockIdx.y, i0 = blockIdx.x * 128;
    const float* Ah = qk + (size_t)h * SEQ * SEQ;
    const int tid = threadIdx.x, lane = tid & 31, wid = tid >> 5;
    const int g = lane >> 2, l = lane & 3;
    const int wm0 = (wid >> 1) * 32, wn0 = (wid & 1) * 32;

    float4 pa[4], pb[2];
    float rsum[4] = {0.f, 0.f, 0.f, 0.f};   // rows tid>>3 + n*32

    auto loadT = [&](int k0) {
        #pragma unroll
        for (int n = 0; n < 4; n++) {
            int f = tid + n * 256, r = f >> 3, c = (f & 7) * 4;
            pa[n] = *(const float4*)(Ah + (size_t)(i0 + r) * SEQ + k0 + c);
        }
        #pragma unroll
        for (int n = 0; n < 2; n++) {
            int f = tid + n * 256, rr = f >> 4, cc = (f & 15) * 4;
            pb[n] = *(const float4*)(v + (size_t)(k0 + rr) * CH + h * DH + cc);
        }
    };
    auto storeT = [&]() {
        #pragma unroll
        for (int n = 0; n < 4; n++) {
            int f = tid + n * 256, r = f >> 3, c = (f & 7) * 4;
            float e0 = __expf(pa[n].x), e1 = __expf(pa[n].y);
            float e2 = __expf(pa[n].z), e3 = __expf(pa[n].w);
            rsum[n] += (e0 + e1) + (e2 + e3);
            sA[r][c] = f2t(e0); sA[r][c + 1] = f2t(e1);
            sA[r][c + 2] = f2t(e2); sA[r][c + 3] = f2t(e3);
        }
        #pragma unroll
        for (int n = 0; n < 2; n++) {
            int f = tid + n * 256, rr = f >> 4, cc = (f & 15) * 4;
            sB[rr][cc] = f2t(pb[n].x); sB[rr][cc + 1] = f2t(pb[n].y);
            sB[rr][cc + 2] = f2t(pb[n].z); sB[rr][cc + 3] = f2t(pb[n].w);
        }
    };

    float acc[2][4][4] = {};
    loadT(0); storeT(); __syncthreads();

    for (int k0 = 0; k0 < SEQ; k0 += 32) {
        bool nx = (k0 + 32) < SEQ;
        if (nx) loadT(k0 + 32);
        #pragma unroll
        for (int ks = 0; ks < 4; ks++) {
            int kk = ks * 8;
            unsigned af[2][4], bf[4][2];
            #pragma unroll
            for (int mt = 0; mt < 2; mt++) {
                int m = wm0 + mt * 16 + g;
                af[mt][0] = sA[m][kk + l];       af[mt][1] = sA[m + 8][kk + l];
                af[mt][2] = sA[m][kk + 4 + l];   af[mt][3] = sA[m + 8][kk + 4 + l];
            }
            #pragma unroll
            for (int nt = 0; nt < 4; nt++) {
                int n = wn0 + nt * 8 + g;
                bf[nt][0] = sB[kk + l][n];       bf[nt][1] = sB[kk + 4 + l][n];
            }
            #pragma unroll
            for (int mt = 0; mt < 2; mt++)
                #pragma unroll
                for (int nt = 0; nt < 4; nt++) mma8(acc[mt][nt], af[mt], bf[nt]);
        }
        __syncthreads();
        if (nx) { storeT(); __syncthreads(); }
    }

    // reduce row denominators: 8 consecutive threads share each row
    #pragma unroll
    for (int n = 0; n < 4; n++) {
        rsum[n] += __shfl_xor_sync(~0u, rsum[n], 1);
        rsum[n] += __shfl_xor_sync(~0u, rsum[n], 2);
        rsum[n] += __shfl_xor_sync(~0u, rsum[n], 4);
    }
    if ((tid & 7) == 0) {
        #pragma unroll
        for (int n = 0; n < 4; n++) s_sum[(tid >> 3) + n * 32] = rsum[n];
    }
    __syncthreads();

    #pragma unroll
    for (int mt = 0; mt < 2; mt++) {
        int mloc = wm0 + mt * 16 + g;
        float inv0 = 1.0f / s_sum[mloc], inv1 = 1.0f / s_sum[mloc + 8];
        #pragma unroll
        for (int nt = 0; nt < 4; nt++) {
            int n = wn0 + nt * 8 + 2 * l;
            *(float2*)(o + (size_t)(i0 + mloc) * CH + h * DH + n) =
                make_float2(acc[mt][nt][0] * inv0, acc[mt][nt][1] * inv0);
            *(float2*)(o + (size_t)(i0 + mloc + 8) * CH + h * DH + n) =
                make_float2(acc[mt][nt][2] * inv1, acc[mt][nt][3] * inv1);
        }
    }
}

// =================================================================================
extern "C" void kernel_launch(void* const* d_in, const int* in_sizes, int n_in,
                              void* d_out, int out_size) {
    const float* x    = (const float*)d_in[0];
    const float* prev = (const float*)d_in[1];
    const float* Wq   = (const float*)d_in[2];
    const float* Wk   = (const float*)d_in[3];
    const float* Wv   = (const float*)d_in[4];
    const float* Wo   = (const float*)d_in[5];
    const float* cq   = (const float*)d_in[6];
    const float* ck   = (const float*)d_in[7];
    const float* cv   = (const float*)d_in[8];
    const float* relw = (const float*)d_in[9];

    float* out0 = (float*)d_out;

    float *xq, *xk, *xv, *q, *k, *v, *o, *qks;
    cudaGetSymbolAddress((void**)&xq, g_xq);
    cudaGetSymbolAddress((void**)&xk, g_xk);
    cudaGetSymbolAddress((void**)&xv, g_xv);
    cudaGetSymbolAddress((void**)&q,  g_q);
    cudaGetSymbolAddress((void**)&k,  g_k);
    cudaGetSymbolAddress((void**)&v,  g_v);
    cudaGetSymbolAddress((void**)&o,  g_o);
    cudaGetSymbolAddress((void**)&qks, g_qk);

    const long long need = (long long)SEQ * CH + (long long)NB * SEQ * SEQ;
    float* qk_dst = ((long long)out_size >= need) ? (out0 + (size_t)SEQ * CH) : qks;

    const int SMEM_QK = (128 * 68 + 64 * 136) * (int)sizeof(unsigned);   // 69632
    cudaFuncSetAttribute(qk_tf32, cudaFuncAttributeMaxDynamicSharedMemorySize, SMEM_QK);

    gemm_xw<<<dim3(CH / 128, SEQ / 128, 3), 256>>>(x, Wq, Wk, Wv, xq, xk, xv);

    dwconv3<<<dim3(SEQ * CH / 256, 3), 256>>>(xq, xk, xv, cq, ck, cv, q, k, v);

    qk_tf32<<<dim3(SEQ / 128, SEQ / 128, NB), 256, SMEM_QK>>>(q, k, relw, prev, qk_dst);

    av_tf32<<<dim3(SEQ / 128, NB), 256>>>(qk_dst, v, o);

    gemm_xw<<<dim3(CH / 128, SEQ / 128, 1), 256>>>(o, Wo, Wo, Wo, out0, out0, out0);
}

// round 11
// speedup vs baseline: 1.4135x; 1.0957x over previous
#include <cuda_runtime.h>
#include <math.h>

constexpr int SEQ  = 2048;
constexpr int CH   = 1024;
constexpr int NB   = 16;
constexpr int DH   = 64;
constexpr int CROP = 2048;

// ---------------- scratch ----------------
__device__ float g_xq[SEQ * CH];
__device__ float g_xk[SEQ * CH];
__device__ float g_xv[SEQ * CH];
__device__ float g_q [SEQ * CH];
__device__ float g_k [SEQ * CH];
__device__ float g_v [SEQ * CH];
__device__ float g_o [SEQ * CH];
__device__ float g_qk[(size_t)NB * SEQ * SEQ];   // fallback if out buffer too small

// ---------------- tf32 helpers ----------------
__device__ __forceinline__ unsigned f2t(float f) {
    unsigned u; asm("cvt.rna.tf32.f32 %0, %1;" : "=r"(u) : "f"(f)); return u;
}
__device__ __forceinline__ void mma8(float c[4], const unsigned a[4], const unsigned b[2]) {
    asm volatile(
        "mma.sync.aligned.m16n8k8.row.col.f32.tf32.tf32.f32 "
        "{%0,%1,%2,%3},{%4,%5,%6,%7},{%8,%9},{%0,%1,%2,%3};"
        : "+f"(c[0]), "+f"(c[1]), "+f"(c[2]), "+f"(c[3])
        : "r"(a[0]), "r"(a[1]), "r"(a[2]), "r"(a[3]), "r"(b[0]), "r"(b[1]));
}

// =================================================================================
// Batched TF32 GEMM: C[z] = A @ B[z], A:[2048x1024], B:[1024x1024] row-major.
// =================================================================================
__global__ __launch_bounds__(256) void gemm_xw(
    const float* __restrict__ A,
    const float* __restrict__ B0, const float* __restrict__ B1, const float* __restrict__ B2,
    float* __restrict__ C0, float* __restrict__ C1, float* __restrict__ C2) {
    __shared__ unsigned sA[128][36];
    __shared__ unsigned sB[32][136];

    const float* B = blockIdx.z == 0 ? B0 : (blockIdx.z == 1 ? B1 : B2);
    float*       C = blockIdx.z == 0 ? C0 : (blockIdx.z == 1 ? C1 : C2);

    const int tid = threadIdx.x, lane = tid & 31, wid = tid >> 5;
    const int i0 = blockIdx.y * 128, j0 = blockIdx.x * 128;
    const int wm0 = (wid >> 2) * 64, wn0 = (wid & 3) * 32;
    const int g = lane >> 2, l = lane & 3;

    float4 pa[4], pb[4];

    auto loadT = [&](int k0) {
        #pragma unroll
        for (int n = 0; n < 4; n++) {
            int f = tid + n * 256, r = f >> 3, c = (f & 7) * 4;
            pa[n] = *(const float4*)(A + (size_t)(i0 + r) * CH + k0 + c);
        }
        #pragma unroll
        for (int n = 0; n < 4; n++) {
            int f = tid + n * 256, r = f >> 5, c = (f & 31) * 4;
            pb[n] = *(const float4*)(B + (size_t)(k0 + r) * CH + j0 + c);
        }
    };
    auto storeT = [&]() {
        #pragma unroll
        for (int n = 0; n < 4; n++) {
            int f = tid + n * 256, r = f >> 3, c = (f & 7) * 4;
            sA[r][c] = f2t(pa[n].x); sA[r][c + 1] = f2t(pa[n].y);
            sA[r][c + 2] = f2t(pa[n].z); sA[r][c + 3] = f2t(pa[n].w);
        }
        #pragma unroll
        for (int n = 0; n < 4; n++) {
            int f = tid + n * 256, r = f >> 5, c = (f & 31) * 4;
            sB[r][c] = f2t(pb[n].x); sB[r][c + 1] = f2t(pb[n].y);
            sB[r][c + 2] = f2t(pb[n].z); sB[r][c + 3] = f2t(pb[n].w);
        }
    };

    float acc[4][4][4] = {};
    loadT(0); storeT(); __syncthreads();

    for (int k0 = 0; k0 < CH; k0 += 32) {
        bool nx = (k0 + 32) < CH;
        if (nx) loadT(k0 + 32);
        #pragma unroll
        for (int ks = 0; ks < 4; ks++) {
            int kk = ks * 8;
            unsigned af[4][4], bf[4][2];
            #pragma unroll
            for (int mt = 0; mt < 4; mt++) {
                int m = wm0 + mt * 16 + g;
                af[mt][0] = sA[m][kk + l];       af[mt][1] = sA[m + 8][kk + l];
                af[mt][2] = sA[m][kk + 4 + l];   af[mt][3] = sA[m + 8][kk + 4 + l];
            }
            #pragma unroll
            for (int nt = 0; nt < 4; nt++) {
                int n = wn0 + nt * 8 + g;
                bf[nt][0] = sB[kk + l][n];       bf[nt][1] = sB[kk + 4 + l][n];
            }
            #pragma unroll
            for (int mt = 0; mt < 4; mt++)
                #pragma unroll
                for (int nt = 0; nt < 4; nt++) mma8(acc[mt][nt], af[mt], bf[nt]);
        }
        __syncthreads();
        if (nx) { storeT(); __syncthreads(); }
    }

    #pragma unroll
    for (int mt = 0; mt < 4; mt++)
        #pragma unroll
        for (int nt = 0; nt < 4; nt++) {
            int m = i0 + wm0 + mt * 16 + g, n = j0 + wn0 + nt * 8 + 2 * l;
            *(float2*)(C + (size_t)m * CH + n) =
                make_float2(acc[mt][nt][0], acc[mt][nt][1]);
            *(float2*)(C + (size_t)(m + 8) * CH + n) =
                make_float2(acc[mt][nt][2], acc[mt][nt][3]);
        }
}

// =================================================================================
// Batched depthwise 3-tap conv.
// =================================================================================
__global__ __launch_bounds__(256) void dwconv3(
    const float* __restrict__ x0, const float* __restrict__ x1, const float* __restrict__ x2,
    const float* __restrict__ w0p, const float* __restrict__ w1p, const float* __restrict__ w2p,
    float* __restrict__ y0, float* __restrict__ y1, float* __restrict__ y2) {
    int z = blockIdx.y;
    const float* x = z == 0 ? x0 : (z == 1 ? x1 : x2);
    const float* wgt = z == 0 ? w0p : (z == 1 ? w1p : w2p);
    float* y = z == 0 ? y0 : (z == 1 ? y1 : y2);

    int idx = blockIdx.x * 256 + threadIdx.x;
    int c = idx & (CH - 1);
    int t = idx >> 10;
    float w0 = wgt[c * 3 + 0], w1 = wgt[c * 3 + 1], w2 = wgt[c * 3 + 2];
    float xm = (t > 0)       ? x[idx - CH] : 0.f;
    float xc = x[idx];
    float xp = (t < SEQ - 1) ? x[idx + CH] : 0.f;
    y[idx] = fmaf(w0, xm, fmaf(w1, xc, w2 * xp));
}

// =================================================================================
// qk kernel (TF32), pipelined BK=32 x 4 steps (gemm_xw skeleton).
// Concatenated K=128 operand generated in staging:
//   A[i][kk] = kk<64 ? q[i, hD+kk]          : relw[kk-64][i]
//   B[kk][j] = kk<64 ? k[j, hD+kk]          : q[j, hD+kk-64]
//   qk[i,j] = (A@B) / 32 + prev[h,i,j]
// Step s covers kk in [32s, 32s+32).
// =================================================================================
__global__ __launch_bounds__(256) void qk_tf32(
    const float* __restrict__ q, const float* __restrict__ k,
    const float* __restrict__ relw, const float* __restrict__ prev,
    float* __restrict__ out) {
    __shared__ unsigned sA[128][36];
    __shared__ unsigned sB[32][136];

    const int h = blockIdx.z, i0 = blockIdx.y * 128, j0 = blockIdx.x * 128;
    const int hD = h * DH;
    const int tid = threadIdx.x, lane = tid & 31, wid = tid >> 5;
    const int g = lane >> 2, l = lane & 3;
    const int wm0 = (wid >> 2) * 64, wn0 = (wid & 3) * 32;

    float4 pa[4], pb[4];

    auto loadT = [&](int s) {
        if (s < 2) {
            #pragma unroll
            for (int n = 0; n < 4; n++) {      // A rows from q, k-range 32s..32s+31
                int f = tid + n * 256, m = f >> 3, c = (f & 7) * 4;
                pa[n] = *(const float4*)(q + (size_t)(i0 + m) * CH + hD + 32 * s + c);
            }
        } else {
            #pragma unroll
            for (int n = 0; n < 4; n++) {      // A from relw (transposed)
                int f = tid + n * 256, dr = f >> 5, i4 = (f & 31) * 4;
                pa[n] = *(const float4*)(relw + (size_t)(32 * (s - 2) + dr) * CROP + i0 + i4);
            }
        }
        const float* src = (s < 2) ? k : q;
        #pragma unroll
        for (int n = 0; n < 4; n++) {          // B cols from k or q
            int f = tid + n * 256, jj = f >> 3, c = (f & 7) * 4;
            pb[n] = *(const float4*)(src + (size_t)(j0 + jj) * CH + hD + 32 * (s & 1) + c);
        }
    };
    auto storeT = [&](int s) {
        if (s < 2) {
            #pragma unroll
            for (int n = 0; n < 4; n++) {
                int f = tid + n * 256, m = f >> 3, c = (f & 7) * 4;
                sA[m][c] = f2t(pa[n].x); sA[m][c + 1] = f2t(pa[n].y);
                sA[m][c + 2] = f2t(pa[n].z); sA[m][c + 3] = f2t(pa[n].w);
            }
        } else {
            #pragma unroll
            for (int n = 0; n < 4; n++) {
                int f = tid + n * 256, dr = f >> 5, i4 = (f & 31) * 4;
                sA[i4][dr] = f2t(pa[n].x); sA[i4 + 1][dr] = f2t(pa[n].y);
                sA[i4 + 2][dr] = f2t(pa[n].z); sA[i4 + 3][dr] = f2t(pa[n].w);
            }
        }
        #pragma unroll
        for (int n = 0; n < 4; n++) {
            int f = tid + n * 256, jj = f >> 3, c = (f & 7) * 4;
            sB[c][jj] = f2t(pb[n].x); sB[c + 1][jj] = f2t(pb[n].y);
            sB[c + 2][jj] = f2t(pb[n].z); sB[c + 3][jj] = f2t(pb[n].w);
        }
    };

    float acc[4][4][4] = {};
    loadT(0); storeT(0); __syncthreads();

    #pragma unroll
    for (int s = 0; s < 4; s++) {
        if (s < 3) loadT(s + 1);
        #pragma unroll
        for (int ks = 0; ks < 4; ks++) {
            int kk = ks * 8;
            unsigned af[4][4], bf[4][2];
            #pragma unroll
            for (int mt = 0; mt < 4; mt++) {
                int m = wm0 + mt * 16 + g;
                af[mt][0] = sA[m][kk + l];       af[mt][1] = sA[m + 8][kk + l];
                af[mt][2] = sA[m][kk + 4 + l];   af[mt][3] = sA[m + 8][kk + 4 + l];
            }
            #pragma unroll
            for (int nt = 0; nt < 4; nt++) {
                int n = wn0 + nt * 8 + g;
                bf[nt][0] = sB[kk + l][n];       bf[nt][1] = sB[kk + 4 + l][n];
            }
            #pragma unroll
            for (int mt = 0; mt < 4; mt++)
                #pragma unroll
                for (int nt = 0; nt < 4; nt++) mma8(acc[mt][nt], af[mt], bf[nt]);
        }
        __syncthreads();
        if (s < 3) { storeT(s + 1); __syncthreads(); }
    }

    const float scale = 0.03125f;   // 1/sqrt(1024)
    #pragma unroll
    for (int mt = 0; mt < 4; mt++)
        #pragma unroll
        for (int nt = 0; nt < 4; nt++) {
            int m = i0 + wm0 + mt * 16 + g, n = j0 + wn0 + nt * 8 + 2 * l;
            size_t o0 = ((size_t)h * SEQ + m) * SEQ + n;
            size_t o1 = o0 + (size_t)8 * SEQ;
            float2 p0 = *(const float2*)(prev + o0);
            float2 p1 = *(const float2*)(prev + o1);
            *(float2*)(out + o0) = make_float2(fmaf(acc[mt][nt][0], scale, p0.x),
                                               fmaf(acc[mt][nt][1], scale, p0.y));
            *(float2*)(out + o1) = make_float2(fmaf(acc[mt][nt][2], scale, p1.x),
                                               fmaf(acc[mt][nt][3], scale, p1.y));
        }
}

// =================================================================================
// AV kernel with on-the-fly softmax: reads qk, computes E=exp(qk) while staging
// tiles, accumulates per-row denominators in registers across the full K loop,
// and normalizes in the epilogue.
//   O[i, h*64+d] = (1/s_i) * sum_j exp(qk[h,i,j]) * v[j, h*64+d]
// =================================================================================
__global__ __launch_bounds__(256) void av_tf32(const float* __restrict__ qk,
                                               const float* __restrict__ v,
                                               float* __restrict__ o) {
    __shared__ unsigned sA[128][36];   // [i][k] tf32 exp(qk)
    __shared__ unsigned sB[32][72];    // [k][d] tf32 v
    __shared__ float s_sum[128];
    const int h = blockIdx.y, i0 = blockIdx.x * 128;
    const float* Ah = qk + (size_t)h * SEQ * SEQ;
    const int tid = threadIdx.x, lane = tid & 31, wid = tid >> 5;
    const int g = lane >> 2, l = lane & 3;
    const int wm0 = (wid >> 1) * 32, wn0 = (wid & 1) * 32;

    float4 pa[4], pb[2];
    float rsum[4] = {0.f, 0.f, 0.f, 0.f};   // rows tid>>3 + n*32

    auto loadT = [&](int k0) {
        #pragma unroll
        for (int n = 0; n < 4; n++) {
            int f = tid + n * 256, r = f >> 3, c = (f & 7) * 4;
            pa[n] = *(const float4*)(Ah + (size_t)(i0 + r) * SEQ + k0 + c);
        }
        #pragma unroll
        for (int n = 0; n < 2; n++) {
            int f = tid + n * 256, rr = f >> 4, cc = (f & 15) * 4;
            pb[n] = *(const float4*)(v + (size_t)(k0 + rr) * CH + h * DH + cc);
        }
    };
    auto storeT = [&]() {
        #pragma unroll
        for (int n = 0; n < 4; n++) {
            int f = tid + n * 256, r = f >> 3, c = (f & 7) * 4;
            float e0 = __expf(pa[n].x), e1 = __expf(pa[n].y);
            float e2 = __expf(pa[n].z), e3 = __expf(pa[n].w);
            rsum[n] += (e0 + e1) + (e2 + e3);
            sA[r][c] = f2t(e0); sA[r][c + 1] = f2t(e1);
            sA[r][c + 2] = f2t(e2); sA[r][c + 3] = f2t(e3);
        }
        #pragma unroll
        for (int n = 0; n < 2; n++) {
            int f = tid + n * 256, rr = f >> 4, cc = (f & 15) * 4;
            sB[rr][cc] = f2t(pb[n].x); sB[rr][cc + 1] = f2t(pb[n].y);
            sB[rr][cc + 2] = f2t(pb[n].z); sB[rr][cc + 3] = f2t(pb[n].w);
        }
    };

    float acc[2][4][4] = {};
    loadT(0); storeT(); __syncthreads();

    for (int k0 = 0; k0 < SEQ; k0 += 32) {
        bool nx = (k0 + 32) < SEQ;
        if (nx) loadT(k0 + 32);
        #pragma unroll
        for (int ks = 0; ks < 4; ks++) {
            int kk = ks * 8;
            unsigned af[2][4], bf[4][2];
            #pragma unroll
            for (int mt = 0; mt < 2; mt++) {
                int m = wm0 + mt * 16 + g;
                af[mt][0] = sA[m][kk + l];       af[mt][1] = sA[m + 8][kk + l];
                af[mt][2] = sA[m][kk + 4 + l];   af[mt][3] = sA[m + 8][kk + 4 + l];
            }
            #pragma unroll
            for (int nt = 0; nt < 4; nt++) {
                int n = wn0 + nt * 8 + g;
                bf[nt][0] = sB[kk + l][n];       bf[nt][1] = sB[kk + 4 + l][n];
            }
            #pragma unroll
            for (int mt = 0; mt < 2; mt++)
                #pragma unroll
                for (int nt = 0; nt < 4; nt++) mma8(acc[mt][nt], af[mt], bf[nt]);
        }
        __syncthreads();
        if (nx) { storeT(); __syncthreads(); }
    }

    // reduce row denominators: 8 consecutive threads share each row
    #pragma unroll
    for (int n = 0; n < 4; n++) {
        rsum[n] += __shfl_xor_sync(~0u, rsum[n], 1);
        rsum[n] += __shfl_xor_sync(~0u, rsum[n], 2);
        rsum[n] += __shfl_xor_sync(~0u, rsum[n], 4);
    }
    if ((tid & 7) == 0) {
        #pragma unroll
        for (int n = 0; n < 4; n++) s_sum[(tid >> 3) + n * 32] = rsum[n];
    }
    __syncthreads();

    #pragma unroll
    for (int mt = 0; mt < 2; mt++) {
        int mloc = wm0 + mt * 16 + g;
        float inv0 = 1.0f / s_sum[mloc], inv1 = 1.0f / s_sum[mloc + 8];
        #pragma unroll
        for (int nt = 0; nt < 4; nt++) {
            int n = wn0 + nt * 8 + 2 * l;
            *(float2*)(o + (size_t)(i0 + mloc) * CH + h * DH + n) =
                make_float2(acc[mt][nt][0] * inv0, acc[mt][nt][1] * inv0);
            *(float2*)(o + (size_t)(i0 + mloc + 8) * CH + h * DH + n) =
                make_float2(acc[mt][nt][2] * inv1, acc[mt][nt][3] * inv1);
        }
    }
}

// =================================================================================
extern "C" void kernel_launch(void* const* d_in, const int* in_sizes, int n_in,
                              void* d_out, int out_size) {
    const float* x    = (const float*)d_in[0];
    const float* prev = (const float*)d_in[1];
    const float* Wq   = (const float*)d_in[2];
    const float* Wk   = (const float*)d_in[3];
    const float* Wv   = (const float*)d_in[4];
    const float* Wo   = (const float*)d_in[5];
    const float* cq   = (const float*)d_in[6];
    const float* ck   = (const float*)d_in[7];
    const float* cv   = (const float*)d_in[8];
    const float* relw = (const float*)d_in[9];

    float* out0 = (float*)d_out;

    float *xq, *xk, *xv, *q, *k, *v, *o, *qks;
    cudaGetSymbolAddress((void**)&xq, g_xq);
    cudaGetSymbolAddress((void**)&xk, g_xk);
    cudaGetSymbolAddress((void**)&xv, g_xv);
    cudaGetSymbolAddress((void**)&q,  g_q);
    cudaGetSymbolAddress((void**)&k,  g_k);
    cudaGetSymbolAddress((void**)&v,  g_v);
    cudaGetSymbolAddress((void**)&o,  g_o);
    cudaGetSymbolAddress((void**)&qks, g_qk);

    const long long need = (long long)SEQ * CH + (long long)NB * SEQ * SEQ;
    float* qk_dst = ((long long)out_size >= need) ? (out0 + (size_t)SEQ * CH) : qks;

    gemm_xw<<<dim3(CH / 128, SEQ / 128, 3), 256>>>(x, Wq, Wk, Wv, xq, xk, xv);

    dwconv3<<<dim3(SEQ * CH / 256, 3), 256>>>(xq, xk, xv, cq, ck, cv, q, k, v);

    qk_tf32<<<dim3(SEQ / 128, SEQ / 128, NB), 256>>>(q, k, relw, prev, qk_dst);

    av_tf32<<<dim3(SEQ / 128, NB), 256>>>(qk_dst, v, o);

    gemm_xw<<<dim3(CH / 128, SEQ / 128, 1), 256>>>(o, Wo, Wo, Wo, out0, out0, out0);
}

// round 15
// speedup vs baseline: 1.4245x; 1.0078x over previous
#include <cuda_runtime.h>
#include <math.h>

constexpr int SEQ  = 2048;
constexpr int CH   = 1024;
constexpr int NB   = 16;
constexpr int DH   = 64;
constexpr int CROP = 2048;

// ---------------- scratch ----------------
__device__ float g_xq[SEQ * CH];
__device__ float g_xk[SEQ * CH];
__device__ float g_xv[SEQ * CH];
__device__ float g_q [SEQ * CH];
__device__ float g_k [SEQ * CH];
__device__ float g_v [SEQ * CH];
__device__ float g_o [SEQ * CH];
__device__ float g_qk[(size_t)NB * SEQ * SEQ];   // fallback if out buffer too small

// ---------------- tf32 helpers ----------------
__device__ __forceinline__ unsigned f2t(float f) {
    unsigned u; asm("cvt.rna.tf32.f32 %0, %1;" : "=r"(u) : "f"(f)); return u;
}
__device__ __forceinline__ void mma8(float c[4], const unsigned a[4], const unsigned b[2]) {
    asm volatile(
        "mma.sync.aligned.m16n8k8.row.col.f32.tf32.tf32.f32 "
        "{%0,%1,%2,%3},{%4,%5,%6,%7},{%8,%9},{%0,%1,%2,%3};"
        : "+f"(c[0]), "+f"(c[1]), "+f"(c[2]), "+f"(c[3])
        : "r"(a[0]), "r"(a[1]), "r"(a[2]), "r"(a[3]), "r"(b[0]), "r"(b[1]));
}

// =================================================================================
// Batched TF32 GEMM: C[z] = A @ B[z]. Double-buffered smem, ONE sync per K-step.
// Dyn smem: sA[2][128][36] + sB[2][32][136] = 71680 B.
// =================================================================================
__global__ __launch_bounds__(256) void gemm_xw(
    const float* __restrict__ A,
    const float* __restrict__ B0, const float* __restrict__ B1, const float* __restrict__ B2,
    float* __restrict__ C0, float* __restrict__ C1, float* __restrict__ C2) {
    extern __shared__ unsigned smem_u[];
    unsigned (*sA)[36]  = (unsigned(*)[36])smem_u;                   // [2*128][36]
    unsigned (*sB)[136] = (unsigned(*)[136])(smem_u + 2 * 128 * 36); // [2*32][136]

    const float* B = blockIdx.z == 0 ? B0 : (blockIdx.z == 1 ? B1 : B2);
    float*       C = blockIdx.z == 0 ? C0 : (blockIdx.z == 1 ? C1 : C2);

    const int tid = threadIdx.x, lane = tid & 31, wid = tid >> 5;
    const int i0 = blockIdx.y * 128, j0 = blockIdx.x * 128;
    const int wm0 = (wid >> 2) * 64, wn0 = (wid & 3) * 32;
    const int g = lane >> 2, l = lane & 3;

    float4 pa[4], pb[4];

    auto loadT = [&](int k0) {
        #pragma unroll
        for (int n = 0; n < 4; n++) {
            int f = tid + n * 256, r = f >> 3, c = (f & 7) * 4;
            pa[n] = *(const float4*)(A + (size_t)(i0 + r) * CH + k0 + c);
        }
        #pragma unroll
        for (int n = 0; n < 4; n++) {
            int f = tid + n * 256, r = f >> 5, c = (f & 31) * 4;
            pb[n] = *(const float4*)(B + (size_t)(k0 + r) * CH + j0 + c);
        }
    };
    auto storeT = [&](int p) {
        unsigned (*dA)[36]  = sA + p * 128;
        unsigned (*dB)[136] = sB + p * 32;
        #pragma unroll
        for (int n = 0; n < 4; n++) {
            int f = tid + n * 256, r = f >> 3, c = (f & 7) * 4;
            dA[r][c] = f2t(pa[n].x); dA[r][c + 1] = f2t(pa[n].y);
            dA[r][c + 2] = f2t(pa[n].z); dA[r][c + 3] = f2t(pa[n].w);
        }
        #pragma unroll
        for (int n = 0; n < 4; n++) {
            int f = tid + n * 256, r = f >> 5, c = (f & 31) * 4;
            dB[r][c] = f2t(pb[n].x); dB[r][c + 1] = f2t(pb[n].y);
            dB[r][c + 2] = f2t(pb[n].z); dB[r][c + 3] = f2t(pb[n].w);
        }
    };

    float acc[4][4][4] = {};
    loadT(0); storeT(0); __syncthreads();

    int p = 0;
    for (int k0 = 0; k0 < CH; k0 += 32) {
        bool nx = (k0 + 32) < CH;
        if (nx) loadT(k0 + 32);
        unsigned (*cA)[36]  = sA + p * 128;
        unsigned (*cB)[136] = sB + p * 32;
        #pragma unroll
        for (int ks = 0; ks < 4; ks++) {
            int kk = ks * 8;
            unsigned af[4][4], bf[4][2];
            #pragma unroll
            for (int mt = 0; mt < 4; mt++) {
                int m = wm0 + mt * 16 + g;
                af[mt][0] = cA[m][kk + l];       af[mt][1] = cA[m + 8][kk + l];
                af[mt][2] = cA[m][kk + 4 + l];   af[mt][3] = cA[m + 8][kk + 4 + l];
            }
            #pragma unroll
            for (int nt = 0; nt < 4; nt++) {
                int n = wn0 + nt * 8 + g;
                bf[nt][0] = cB[kk + l][n];       bf[nt][1] = cB[kk + 4 + l][n];
            }
            #pragma unroll
            for (int mt = 0; mt < 4; mt++)
                #pragma unroll
                for (int nt = 0; nt < 4; nt++) mma8(acc[mt][nt], af[mt], bf[nt]);
        }
        if (nx) storeT(p ^ 1);
        __syncthreads();
        p ^= 1;
    }

    #pragma unroll
    for (int mt = 0; mt < 4; mt++)
        #pragma unroll
        for (int nt = 0; nt < 4; nt++) {
            int m = i0 + wm0 + mt * 16 + g, n = j0 + wn0 + nt * 8 + 2 * l;
            *(float2*)(C + (size_t)m * CH + n) =
                make_float2(acc[mt][nt][0], acc[mt][nt][1]);
            *(float2*)(C + (size_t)(m + 8) * CH + n) =
                make_float2(acc[mt][nt][2], acc[mt][nt][3]);
        }
}

// =================================================================================
// Batched depthwise 3-tap conv.
// =================================================================================
__global__ __launch_bounds__(256) void dwconv3(
    const float* __restrict__ x0, const float* __restrict__ x1, const float* __restrict__ x2,
    const float* __restrict__ w0p, const float* __restrict__ w1p, const float* __restrict__ w2p,
    float* __restrict__ y0, float* __restrict__ y1, float* __restrict__ y2) {
    int z = blockIdx.y;
    const float* x = z == 0 ? x0 : (z == 1 ? x1 : x2);
    const float* wgt = z == 0 ? w0p : (z == 1 ? w1p : w2p);
    float* y = z == 0 ? y0 : (z == 1 ? y1 : y2);

    int idx = blockIdx.x * 256 + threadIdx.x;
    int c = idx & (CH - 1);
    int t = idx >> 10;
    float w0 = wgt[c * 3 + 0], w1 = wgt[c * 3 + 1], w2 = wgt[c * 3 + 2];
    float xm = (t > 0)       ? x[idx - CH] : 0.f;
    float xc = x[idx];
    float xp = (t < SEQ - 1) ? x[idx + CH] : 0.f;
    y[idx] = fmaf(w0, xm, fmaf(w1, xc, w2 * xp));
}

// =================================================================================
// qk kernel (TF32), pipelined BK=32 x 4 steps, double-buffered (one sync/step).
//   A[i][kk] = kk<64 ? q[i, hD+kk] : relw[kk-64][i]
//   B[kk][j] = kk<64 ? k[j, hD+kk] : q[j, hD+kk-64]
//   qk[i,j] = (A@B) / 32 + prev[h,i,j]
// Dyn smem: sA[2][128][36] + sB[2][32][136] = 71680 B.
// =================================================================================
__global__ __launch_bounds__(256) void qk_tf32(
    const float* __restrict__ q, const float* __restrict__ k,
    const float* __restrict__ relw, const float* __restrict__ prev,
    float* __restrict__ out) {
    extern __shared__ unsigned smem_u[];
    unsigned (*sA)[36]  = (unsigned(*)[36])smem_u;                   // [2*128][36]
    unsigned (*sB)[136] = (unsigned(*)[136])(smem_u + 2 * 128 * 36); // [2*32][136]

    const int h = blockIdx.z, i0 = blockIdx.y * 128, j0 = blockIdx.x * 128;
    const int hD = h * DH;
    const int tid = threadIdx.x, lane = tid & 31, wid = tid >> 5;
    const int g = lane >> 2, l = lane & 3;
    const int wm0 = (wid >> 2) * 64, wn0 = (wid & 3) * 32;

    float4 pa[4], pb[4];

    auto loadT = [&](int s) {
        if (s < 2) {
            #pragma unroll
            for (int n = 0; n < 4; n++) {      // A rows from q
                int f = tid + n * 256, m = f >> 3, c = (f & 7) * 4;
                pa[n] = *(const float4*)(q + (size_t)(i0 + m) * CH + hD + 32 * s + c);
            }
        } else {
            #pragma unroll
            for (int n = 0; n < 4; n++) {      // A from relw (transposed)
                int f = tid + n * 256, dr = f >> 5, i4 = (f & 31) * 4;
                pa[n] = *(const float4*)(relw + (size_t)(32 * (s - 2) + dr) * CROP + i0 + i4);
            }
        }
        const float* src = (s < 2) ? k : q;
        #pragma unroll
        for (int n = 0; n < 4; n++) {          // B cols from k or q
            int f = tid + n * 256, jj = f >> 3, c = (f & 7) * 4;
            pb[n] = *(const float4*)(src + (size_t)(j0 + jj) * CH + hD + 32 * (s & 1) + c);
        }
    };
    auto storeT = [&](int s, int p) {
        unsigned (*dA)[36]  = sA + p * 128;
        unsigned (*dB)[136] = sB + p * 32;
        if (s < 2) {
            #pragma unroll
            for (int n = 0; n < 4; n++) {
                int f = tid + n * 256, m = f >> 3, c = (f & 7) * 4;
                dA[m][c] = f2t(pa[n].x); dA[m][c + 1] = f2t(pa[n].y);
                dA[m][c + 2] = f2t(pa[n].z); dA[m][c + 3] = f2t(pa[n].w);
            }
        } else {
            #pragma unroll
            for (int n = 0; n < 4; n++) {
                int f = tid + n * 256, dr = f >> 5, i4 = (f & 31) * 4;
                dA[i4][dr] = f2t(pa[n].x); dA[i4 + 1][dr] = f2t(pa[n].y);
                dA[i4 + 2][dr] = f2t(pa[n].z); dA[i4 + 3][dr] = f2t(pa[n].w);
            }
        }
        #pragma unroll
        for (int n = 0; n < 4; n++) {
            int f = tid + n * 256, jj = f >> 3, c = (f & 7) * 4;
            dB[c][jj] = f2t(pb[n].x); dB[c + 1][jj] = f2t(pb[n].y);
            dB[c + 2][jj] = f2t(pb[n].z); dB[c + 3][jj] = f2t(pb[n].w);
        }
    };

    float acc[4][4][4] = {};
    loadT(0); storeT(0, 0); __syncthreads();

    int p = 0;
    #pragma unroll
    for (int s = 0; s < 4; s++) {
        if (s < 3) loadT(s + 1);
        unsigned (*cA)[36]  = sA + p * 128;
        unsigned (*cB)[136] = sB + p * 32;
        #pragma unroll
        for (int ks = 0; ks < 4; ks++) {
            int kk = ks * 8;
            unsigned af[4][4], bf[4][2];
            #pragma unroll
            for (int mt = 0; mt < 4; mt++) {
                int m = wm0 + mt * 16 + g;
                af[mt][0] = cA[m][kk + l];       af[mt][1] = cA[m + 8][kk + l];
                af[mt][2] = cA[m][kk + 4 + l];   af[mt][3] = cA[m + 8][kk + 4 + l];
            }
            #pragma unroll
            for (int nt = 0; nt < 4; nt++) {
                int n = wn0 + nt * 8 + g;
                bf[nt][0] = cB[kk + l][n];       bf[nt][1] = cB[kk + 4 + l][n];
            }
            #pragma unroll
            for (int mt = 0; mt < 4; mt++)
                #pragma unroll
                for (int nt = 0; nt < 4; nt++) mma8(acc[mt][nt], af[mt], bf[nt]);
        }
        if (s < 3) { storeT(s + 1, p ^ 1); __syncthreads(); }
        p ^= 1;
    }

    const float scale = 0.03125f;   // 1/sqrt(1024)
    #pragma unroll
    for (int mt = 0; mt < 4; mt++)
        #pragma unroll
        for (int nt = 0; nt < 4; nt++) {
            int m = i0 + wm0 + mt * 16 + g, n = j0 + wn0 + nt * 8 + 2 * l;
            size_t o0 = ((size_t)h * SEQ + m) * SEQ + n;
            size_t o1 = o0 + (size_t)8 * SEQ;
            float2 p0 = *(const float2*)(prev + o0);
            float2 p1 = *(const float2*)(prev + o1);
            *(float2*)(out + o0) = make_float2(fmaf(acc[mt][nt][0], scale, p0.x),
                                               fmaf(acc[mt][nt][1], scale, p0.y));
            *(float2*)(out + o1) = make_float2(fmaf(acc[mt][nt][2], scale, p1.x),
                                               fmaf(acc[mt][nt][3], scale, p1.y));
        }
}

// =================================================================================
// AV kernel with on-the-fly softmax, double-buffered (one sync/step).
//   O[i, h*64+d] = (1/s_i) * sum_j exp(qk[h,i,j]) * v[j, h*64+d]
// Dyn smem: sA[2][128][36] + sB[2][32][72] = 55296 B.
// =================================================================================
__global__ __launch_bounds__(256) void av_tf32(const float* __restrict__ qk,
                                               const float* __restrict__ v,
                                               float* __restrict__ o) {
    extern __shared__ unsigned smem_u[];
    unsigned (*sA)[36] = (unsigned(*)[36])smem_u;                    // [2*128][36]
    unsigned (*sB)[72] = (unsigned(*)[72])(smem_u + 2 * 128 * 36);   // [2*32][72]
    __shared__ float s_sum[128];

    const int h = blockIdx.y, i0 = blockIdx.x * 128;
    const float* Ah = qk + (size_t)h * SEQ * SEQ;
    const int tid = threadIdx.x, lane = tid & 31, wid = tid >> 5;
    const int g = lane >> 2, l = lane & 3;
    const int wm0 = (wid >> 1) * 32, wn0 = (wid & 1) * 32;

    float4 pa[4], pb[2];
    float rsum[4] = {0.f, 0.f, 0.f, 0.f};   // rows tid>>3 + n*32

    auto loadT = [&](int k0) {
        #pragma unroll
        for (int n = 0; n < 4; n++) {
            int f = tid + n * 256, r = f >> 3, c = (f & 7) * 4;
            pa[n] = *(const float4*)(Ah + (size_t)(i0 + r) * SEQ + k0 + c);
        }
        #pragma unroll
        for (int n = 0; n < 2; n++) {
            int f = tid + n * 256, rr = f >> 4, cc = (f & 15) * 4;
            pb[n] = *(const float4*)(v + (size_t)(k0 + rr) * CH + h * DH + cc);
        }
    };
    auto storeT = [&](int p) {
        unsigned (*dA)[36] = sA + p * 128;
        unsigned (*dB)[72] = sB + p * 32;
        #pragma unroll
        for (int n = 0; n < 4; n++) {
            int f = tid + n * 256, r = f >> 3, c = (f & 7) * 4;
            float e0 = __expf(pa[n].x), e1 = __expf(pa[n].y);
            float e2 = __expf(pa[n].z), e3 = __expf(pa[n].w);
            rsum[n] += (e0 + e1) + (e2 + e3);
            dA[r][c] = f2t(e0); dA[r][c + 1] = f2t(e1);
            dA[r][c + 2] = f2t(e2); dA[r][c + 3] = f2t(e3);
        }
        #pragma unroll
        for (int n = 0; n < 2; n++) {
            int f = tid + n * 256, rr = f >> 4, cc = (f & 15) * 4;
            dB[rr][cc] = f2t(pb[n].x); dB[rr][cc + 1] = f2t(pb[n].y);
            dB[rr][cc + 2] = f2t(pb[n].z); dB[rr][cc + 3] = f2t(pb[n].w);
        }
    };

    float acc[2][4][4] = {};
    loadT(0); storeT(0); __syncthreads();

    int p = 0;
    for (int k0 = 0; k0 < SEQ; k0 += 32) {
        bool nx = (k0 + 32) < SEQ;
        if (nx) loadT(k0 + 32);
        unsigned (*cA)[36] = sA + p * 128;
        unsigned (*cB)[72] = sB + p * 32;
        #pragma unroll
        for (int ks = 0; ks < 4; ks++) {
            int kk = ks * 8;
            unsigned af[2][4], bf[4][2];
            #pragma unroll
            for (int mt = 0; mt < 2; mt++) {
                int m = wm0 + mt * 16 + g;
                af[mt][0] = cA[m][kk + l];       af[mt][1] = cA[m + 8][kk + l];
                af[mt][2] = cA[m][kk + 4 + l];   af[mt][3] = cA[m + 8][kk + 4 + l];
            }
            #pragma unroll
            for (int nt = 0; nt < 4; nt++) {
                int n = wn0 + nt * 8 + g;
                bf[nt][0] = cB[kk + l][n];       bf[nt][1] = cB[kk + 4 + l][n];
            }
            #pragma unroll
            for (int mt = 0; mt < 2; mt++)
                #pragma unroll
                for (int nt = 0; nt < 4; nt++) mma8(acc[mt][nt], af[mt], bf[nt]);
        }
        if (nx) storeT(p ^ 1);
        __syncthreads();
        p ^= 1;
    }

    // reduce row denominators: 8 consecutive threads share each row
    #pragma unroll
    for (int n = 0; n < 4; n++) {
        rsum[n] += __shfl_xor_sync(~0u, rsum[n], 1);
        rsum[n] += __shfl_xor_sync(~0u, rsum[n], 2);
        rsum[n] += __shfl_xor_sync(~0u, rsum[n], 4);
    }
    if ((tid & 7) == 0) {
        #pragma unroll
        for (int n = 0; n < 4; n++) s_sum[(tid >> 3) + n * 32] = rsum[n];
    }
    __syncthreads();

    #pragma unroll
    for (int mt = 0; mt < 2; mt++) {
        int mloc = wm0 + mt * 16 + g;
        float inv0 = 1.0f / s_sum[mloc], inv1 = 1.0f / s_sum[mloc + 8];
        #pragma unroll
        for (int nt = 0; nt < 4; nt++) {
            int n = wn0 + nt * 8 + 2 * l;
            *(float2*)(o + (size_t)(i0 + mloc) * CH + h * DH + n) =
                make_float2(acc[mt][nt][0] * inv0, acc[mt][nt][1] * inv0);
            *(float2*)(o + (size_t)(i0 + mloc + 8) * CH + h * DH + n) =
                make_float2(acc[mt][nt][2] * inv1, acc[mt][nt][3] * inv1);
        }
    }
}

// =================================================================================
extern "C" void kernel_launch(void* const* d_in, const int* in_sizes, int n_in,
                              void* d_out, int out_size) {
    const float* x    = (const float*)d_in[0];
    const float* prev = (const float*)d_in[1];
    const float* Wq   = (const float*)d_in[2];
    const float* Wk   = (const float*)d_in[3];
    const float* Wv   = (const float*)d_in[4];
    const float* Wo   = (const float*)d_in[5];
    const float* cq   = (const float*)d_in[6];
    const float* ck   = (const float*)d_in[7];
    const float* cv   = (const float*)d_in[8];
    const float* relw = (const float*)d_in[9];

    float* out0 = (float*)d_out;

    float *xq, *xk, *xv, *q, *k, *v, *o, *qks;
    cudaGetSymbolAddress((void**)&xq, g_xq);
    cudaGetSymbolAddress((void**)&xk, g_xk);
    cudaGetSymbolAddress((void**)&xv, g_xv);
    cudaGetSymbolAddress((void**)&q,  g_q);
    cudaGetSymbolAddress((void**)&k,  g_k);
    cudaGetSymbolAddress((void**)&v,  g_v);
    cudaGetSymbolAddress((void**)&o,  g_o);
    cudaGetSymbolAddress((void**)&qks, g_qk);

    const long long need = (long long)SEQ * CH + (long long)NB * SEQ * SEQ;
    float* qk_dst = ((long long)out_size >= need) ? (out0 + (size_t)SEQ * CH) : qks;

    const int SMEM_G  = (2 * 128 * 36 + 2 * 32 * 136) * (int)sizeof(unsigned);  // 71680
    const int SMEM_AV = (2 * 128 * 36 + 2 * 32 * 72) * (int)sizeof(unsigned);   // 55296
    cudaFuncSetAttribute(gemm_xw, cudaFuncAttributeMaxDynamicSharedMemorySize, SMEM_G);
    cudaFuncSetAttribute(qk_tf32, cudaFuncAttributeMaxDynamicSharedMemorySize, SMEM_G);
    cudaFuncSetAttribute(av_tf32, cudaFuncAttributeMaxDynamicSharedMemorySize, SMEM_AV);

    gemm_xw<<<dim3(CH / 128, SEQ / 128, 3), 256, SMEM_G>>>(x, Wq, Wk, Wv, xq, xk, xv);

    dwconv3<<<dim3(SEQ * CH / 256, 3), 256>>>(xq, xk, xv, cq, ck, cv, q, k, v);

    qk_tf32<<<dim3(SEQ / 128, SEQ / 128, NB), 256, SMEM_G>>>(q, k, relw, prev, qk_dst);

    av_tf32<<<dim3(SEQ / 128, NB), 256, SMEM_AV>>>(qk_dst, v, o);

    gemm_xw<<<dim3(CH / 128, SEQ / 128, 1), 256, SMEM_G>>>(o, Wo, Wo, Wo, out0, out0, out0);
}